// round 11
// baseline (speedup 1.0000x reference)
#include <cuda_runtime.h>
#include <cuda_bf16.h>
#include <cstdint>

typedef unsigned long long ull;
typedef long long ll;
typedef unsigned short u16;
typedef unsigned int u32;

#define UDIM 1024
#define BATCH 32
#define TDIM 2048
#define CH 16
#define NCH (TDIM / CH)          // 128
#define SLE (1024 * 1024)        // one UxU matrix, elements

// ---------------- scratch (device globals; no runtime alloc) ----------------
__device__ u16   g_Xhi[(size_t)BATCH * TDIM * UDIM];
__device__ u16   g_Xlo[(size_t)BATCH * TDIM * UDIM];
__device__ u16   g_UAhi[NCH * BATCH * UDIM], g_UAlo[NCH * BATCH * UDIM];
__device__ u16   g_UBhi[NCH * BATCH * UDIM], g_UBlo[NCH * BATCH * UDIM];
__device__ u16   g_KThi[SLE], g_KTlo[SLE];
__device__ u16   g_SPhi[CH * SLE], g_SPlo[CH * SLE];    // S^1..S^16
__device__ u16   g_S32hi[SLE], g_S32lo[SLE];            // S^32
__device__ u16   g_S64hi[SLE], g_S64lo[SLE];            // S^64
__device__ u16   g_RPhi[7 * SLE], g_RPlo[7 * SLE];      // R^1,2,4,8,16,32,64
__device__ u16   g_C1hi[64 * BATCH * UDIM], g_C1lo[64 * BATCH * UDIM];
__device__ u16   g_C2hi[32 * BATCH * UDIM], g_C2lo[32 * BATCH * UDIM];
__device__ u16   g_GChi[NCH * BATCH * UDIM], g_GClo[NCH * BATCH * UDIM];
__device__ float g_W8F[SLE];                // S^128 fp32 (serial chain weight)
__device__ float g_sP1[64 * BATCH * UDIM];
__device__ float g_sP2[32 * BATCH * UDIM];
__device__ float g_sP3[16 * BATCH * UDIM];
__device__ float g_gbuf[NCH * BATCH * UDIM];

#define MAX_BAR 2048
__device__ volatile unsigned g_bar[MAX_BAR];

__global__ void __launch_bounds__(256) bar_reset_kernel() {
    int i = blockIdx.x * blockDim.x + threadIdx.x;
    if (i < MAX_BAR) *(unsigned*)&g_bar[i] = 0u;
}

// ---------------- helpers ----------------
__device__ __forceinline__ u32 smem_u32(const void* p) {
    u32 a;
    asm("{ .reg .u64 t; cvta.to.shared.u64 t, %1; cvt.u32.u64 %0, t; }"
        : "=r"(a) : "l"(p));
    return a;
}
#define SWZ(o) ((o) ^ (((o) >> 3) & 0x70))

__device__ __forceinline__ void bsplit(float v, u16& h, u16& l) {
    __nv_bfloat16 bh = __float2bfloat16_rn(v);
    float r = v - __bfloat162float(bh);
    __nv_bfloat16 bl = __float2bfloat16_rn(r);
    h = __bfloat16_as_ushort(bh);
    l = __bfloat16_as_ushort(bl);
}

__global__ void __launch_bounds__(256) copy_h0_kernel(
    const float* __restrict__ h0, float* __restrict__ g,
    u16* __restrict__ GCh, u16* __restrict__ GCl)
{
    int i = blockIdx.x * blockDim.x + threadIdx.x;
    if (i < BATCH * UDIM) {
        float v = h0[i];
        g[i] = v;
        u16 h, l;
        bsplit(v, h, l);
        GCh[i] = h; GCl[i] = l;
    }
}

__device__ __forceinline__ void ldsm4(u32 addr, u32& r0, u32& r1, u32& r2, u32& r3) {
    asm volatile("ldmatrix.sync.aligned.m8n8.x4.shared.b16 {%0,%1,%2,%3}, [%4];"
                 : "=r"(r0), "=r"(r1), "=r"(r2), "=r"(r3) : "r"(addr));
}
__device__ __forceinline__ void mma16816(float* d, const u32* a, const u32* b) {
    asm volatile(
        "mma.sync.aligned.m16n8k16.row.col.f32.bf16.bf16.f32 "
        "{%0,%1,%2,%3}, {%4,%5,%6,%7}, {%8,%9}, {%0,%1,%2,%3};"
        : "+f"(d[0]), "+f"(d[1]), "+f"(d[2]), "+f"(d[3])
        : "r"(a[0]), "r"(a[1]), "r"(a[2]), "r"(a[3]), "r"(b[0]), "r"(b[1]));
}

// ------------- split_gather: fp32 strided rows -> bf16 hi/lo natural -------
__global__ void __launch_bounds__(256) split_gather_kernel(
    const float* __restrict__ src, ll sB, ll sC,
    u16* __restrict__ hi, u16* __restrict__ lo)
{
    int m = blockIdx.x;
    int k = threadIdx.x * 4;
    ll off = (ll)(m & 31) * sB + (ll)(m >> 5) * sC + k;
    float4 v = *(const float4*)(src + off);
    u16 h0, h1, h2, h3, l0, l1, l2, l3;
    bsplit(v.x, h0, l0); bsplit(v.y, h1, l1);
    bsplit(v.z, h2, l2); bsplit(v.w, h3, l3);
    ll doff = (ll)m * 1024 + k;
    *(ushort4*)(hi + doff) = make_ushort4(h0, h1, h2, h3);
    *(ushort4*)(lo + doff) = make_ushort4(l0, l1, l2, l3);
}

// ------------- transpose_split: fp32 W[k][n] -> bf16 hi/lo of W^T [n][k] ----
__global__ void __launch_bounds__(256) transpose_split_kernel(
    const float* __restrict__ src, u16* __restrict__ thi, u16* __restrict__ tlo)
{
    __shared__ float tile[32][33];
    int bx = blockIdx.x * 32;
    int by = blockIdx.y * 32;
    int tx = threadIdx.x & 31;
    int ty = threadIdx.x >> 5;
#pragma unroll
    for (int i = 0; i < 32; i += 8)
        tile[ty + i][tx] = src[(ll)(by + ty + i) * 1024 + bx + tx];
    __syncthreads();
#pragma unroll
    for (int i = 0; i < 32; i += 8) {
        u16 h, l;
        bsplit(tile[tx][ty + i], h, l);
        ll off = (ll)(bx + ty + i) * 1024 + (by + tx);
        thi[off] = h;
        tlo[off] = l;
    }
}

// ---------------------------------------------------------------------------
// tgemm (operand-shared split): C[m][n] = sum_k Af[m][k]*Bf[n][k].
// K loop over base K=1024 in 16 chunks of 64. Each stage holds Ahi/Alo/Bhi/Blo
// (4 x 16KB = 64KB); per k16 the 3 split products (hi*hi, hi*lo, lo*hi) run
// against the SAME resident tiles -> 3x less smem write traffic, 1.5x less
// gmem, fragment-register reuse across regions. 3 stages, 1 CTA/SM (192KB).
// Row mappings: (m&31)*SB + (m>>5)*SC for A/Add/OutF/OB. B natural [n][k].
// ---------------------------------------------------------------------------
#define TG_STAGE 65536
#define TG_SMEM (3 * TG_STAGE)
#define TG_NCHK 16

__global__ void __launch_bounds__(256, 1) tgemm_kernel(
    const u16* __restrict__ Ahi, const u16* __restrict__ Alo, ll aSB, ll aSC,
    const u16* __restrict__ Bhi, const u16* __restrict__ Blo,
    const float* __restrict__ Add, ll adSB, ll adSC,
    float* __restrict__ OutF, ll ofSB, ll ofSC,
    u16* __restrict__ OBhi, u16* __restrict__ OBlo, ll obSB, ll obSC)
{
    extern __shared__ char smraw[];
    const u32 smbase = smem_u32(smraw);

    const int tid  = threadIdx.x;
    const int wid  = tid >> 5;
    const int lane = tid & 31;
    const ll mBase = (ll)blockIdx.y * 128;
    const ll nBase = (ll)blockIdx.x * 128;

    const int wm = (wid >> 1) * 32;
    const int wn = (wid & 1) * 64;

    float acc[2][8][4];
#pragma unroll
    for (int i = 0; i < 2; i++)
#pragma unroll
        for (int j = 0; j < 8; j++)
#pragma unroll
            for (int q = 0; q < 4; q++) acc[i][j][q] = 0.0f;

    auto load_chunk = [&](int c, int s) {
        const ll kbase = (ll)c * 64;
        u32 base = smbase + (u32)s * TG_STAGE;
#pragma unroll
        for (int i = 0; i < 4; i++) {
            int idx = i * 256 + tid;
            int row = idx >> 3;
            int cc  = (idx & 7) * 16;
            ll  kel = kbase + (idx & 7) * 8;
            u32 sw  = SWZ((u32)(row * 128 + cc));
            ll  rm  = mBase + row;
            ll  aoff = (rm & 31) * aSB + (rm >> 5) * aSC + kel;
            ll  boff = (nBase + row) * 1024 + kel;
            asm volatile("cp.async.cg.shared.global [%0], [%1], 16;"
                :: "r"(base + sw), "l"((ull)(uintptr_t)(Ahi + aoff)));
            asm volatile("cp.async.cg.shared.global [%0], [%1], 16;"
                :: "r"(base + 16384 + sw), "l"((ull)(uintptr_t)(Alo + aoff)));
            asm volatile("cp.async.cg.shared.global [%0], [%1], 16;"
                :: "r"(base + 32768 + sw), "l"((ull)(uintptr_t)(Bhi + boff)));
            asm volatile("cp.async.cg.shared.global [%0], [%1], 16;"
                :: "r"(base + 49152 + sw), "l"((ull)(uintptr_t)(Blo + boff)));
        }
        asm volatile("cp.async.commit_group;" ::: "memory");
    };

    load_chunk(0, 0);
    load_chunk(1, 1);

    const int aRow = (lane & 15);
    const int aKb  = (lane >> 4) * 16;
    const int bRow = (lane & 7) + ((lane >> 4) << 3);
    const int bKb  = ((lane >> 3) & 1) * 16;

#pragma unroll 1
    for (int c = 0; c < TG_NCHK; c++) {
        if (c + 2 < TG_NCHK) {
            asm volatile("cp.async.wait_group 1;" ::: "memory");
        } else {
            asm volatile("cp.async.wait_group 0;" ::: "memory");
        }
        __syncthreads();
        if (c + 2 < TG_NCHK) load_chunk(c + 2, (c + 2) % 3);

        u32 base = smbase + (u32)(c % 3) * TG_STAGE;

#pragma unroll
        for (int k16 = 0; k16 < 4; k16++) {
            const int kb = k16 * 32;
            // hi*hi
            u32 ah[2][4];
#pragma unroll
            for (int i = 0; i < 2; i++) {
                u32 ad = base + SWZ((u32)((wm + i * 16 + aRow) * 128 + kb + aKb));
                ldsm4(ad, ah[i][0], ah[i][1], ah[i][2], ah[i][3]);
            }
            u32 bh[4][4];
#pragma unroll
            for (int j16 = 0; j16 < 4; j16++) {
                u32 bd = base + 32768 +
                         SWZ((u32)((wn + j16 * 16 + bRow) * 128 + kb + bKb));
                ldsm4(bd, bh[j16][0], bh[j16][1], bh[j16][2], bh[j16][3]);
            }
#pragma unroll
            for (int i = 0; i < 2; i++)
#pragma unroll
                for (int j = 0; j < 8; j++)
                    mma16816(acc[i][j], ah[i], &bh[j >> 1][(j & 1) * 2]);

            // hi*lo  (reuse ah)
            u32 bl[4][4];
#pragma unroll
            for (int j16 = 0; j16 < 4; j16++) {
                u32 bd = base + 49152 +
                         SWZ((u32)((wn + j16 * 16 + bRow) * 128 + kb + bKb));
                ldsm4(bd, bl[j16][0], bl[j16][1], bl[j16][2], bl[j16][3]);
            }
#pragma unroll
            for (int i = 0; i < 2; i++)
#pragma unroll
                for (int j = 0; j < 8; j++)
                    mma16816(acc[i][j], ah[i], &bl[j >> 1][(j & 1) * 2]);

            // lo*hi  (reuse bh)
            u32 al[2][4];
#pragma unroll
            for (int i = 0; i < 2; i++) {
                u32 ad = base + 16384 +
                         SWZ((u32)((wm + i * 16 + aRow) * 128 + kb + aKb));
                ldsm4(ad, al[i][0], al[i][1], al[i][2], al[i][3]);
            }
#pragma unroll
            for (int i = 0; i < 2; i++)
#pragma unroll
                for (int j = 0; j < 8; j++)
                    mma16816(acc[i][j], al[i], &bh[j >> 1][(j & 1) * 2]);
        }
    }

    const int g  = lane >> 2;
    const int tg = (lane & 3) * 2;

#pragma unroll
    for (int i = 0; i < 2; i++) {
#pragma unroll
        for (int half = 0; half < 2; half++) {
            ll m = mBase + wm + i * 16 + g + half * 8;
            ll roff = (m & 31);
            ll coff = (m >> 5);
            const float* addp = Add ?
                Add + roff * adSB + coff * adSC + nBase : (const float*)0;
            float* ofp = OutF ?
                OutF + roff * ofSB + coff * ofSC + nBase : (float*)0;
            u16* obh = OBhi ? OBhi + roff * obSB + coff * obSC + nBase : (u16*)0;
            u16* obl = OBlo ? OBlo + roff * obSB + coff * obSC + nBase : (u16*)0;
#pragma unroll
            for (int j = 0; j < 8; j++) {
                int n = wn + j * 8 + tg;
                float v0 = acc[i][j][half * 2 + 0];
                float v1 = acc[i][j][half * 2 + 1];
                if (addp) {
                    float2 a = *(const float2*)(addp + n);
                    v0 += a.x; v1 += a.y;
                }
                if (ofp)
                    *(float2*)(ofp + n) = make_float2(v0, v1);
                if (obh) {
                    u16 h0, h1, l0, l1;
                    bsplit(v0, h0, l0);
                    bsplit(v1, h1, l1);
                    *(ushort2*)(obh + n) = make_ushort2(h0, h1);
                    *(ushort2*)(obl + n) = make_ushort2(l0, l1);
                }
            }
        }
    }
}

// ---------------------------------------------------------------------------
// phase2: serial carry chain G[c+1] = G[c] @ W + u[c]; emits bf16 split of
// each produced state into GC at stride gcStep.
// ---------------------------------------------------------------------------
__device__ __forceinline__ void ffma2(ull& d, ull a, ull b) {
    asm volatile("fma.rn.f32x2 %0, %1, %2, %0;" : "+l"(d) : "l"(a), "l"(b));
}
__device__ __forceinline__ float2 u2f2(ull v) {
    float2 f;
    f.x = __uint_as_float((unsigned)(v & 0xffffffffull));
    f.y = __uint_as_float((unsigned)(v >> 32));
    return f;
}
__device__ __forceinline__ float4 ldcg4(const float* p) {
    float4 v;
    asm volatile("ld.global.cg.v4.f32 {%0,%1,%2,%3}, [%4];"
                 : "=f"(v.x), "=f"(v.y), "=f"(v.z), "=f"(v.w) : "l"(p));
    return v;
}
#define P2_RPAD 1028
#define P2_HPAD 1032
#define P2_HS_OFF (32 * P2_RPAD)
#define P2_SMEM_FLOATS (32 * P2_RPAD + 8 * P2_HPAD)
#define P2_CTAS 128

__global__ void __launch_bounds__(256) phase2_kernel(
    const float* __restrict__ ST,
    const float* __restrict__ u, ll uSB, ll uSC,
    float* __restrict__ g, ll gStep,
    u16* __restrict__ GCh, u16* __restrict__ GCl, ll gcStep,
    int steps)
{
    extern __shared__ float sm[];
    const int tid = threadIdx.x;
    const int col0 = (blockIdx.x & 31) * 32;
    const int b0   = (blockIdx.x >> 5) * 8;

    for (int idx = tid; idx < 32 * 1024; idx += 256) {
        int j = idx >> 10, k = idx & 1023;
        sm[j * P2_RPAD + k] = ST[(size_t)(col0 + j) * 1024 + k];
    }
    __syncthreads();

    const int j = tid & 31;
    const int b = tid >> 5;
    const float* Rrow = &sm[j * P2_RPAD];
    const float* hrow = &sm[P2_HS_OFF + b * P2_HPAD];
    const unsigned P = gridDim.x;

    for (int c = 0; c < steps; c++) {
        const float* gsrc = g + (ll)c * gStep;
        for (int i = tid; i < 2048; i += 256) {
            int bb = i >> 8, kk = (i & 255) * 4;
            float4 v = ldcg4(gsrc + (size_t)(b0 + bb) * UDIM + kk);
            *(float4*)&sm[P2_HS_OFF + bb * P2_HPAD + kk] = v;
        }
        __syncthreads();

        ull a0 = 0, a1 = 0, a2 = 0, a3 = 0;
#pragma unroll 4
        for (int k = 0; k < 1024; k += 8) {
            ulonglong2 h01 = *(const ulonglong2*)(hrow + k);
            ulonglong2 h23 = *(const ulonglong2*)(hrow + k + 4);
            ulonglong2 r01 = *(const ulonglong2*)(Rrow + k);
            ulonglong2 r23 = *(const ulonglong2*)(Rrow + k + 4);
            ffma2(a0, h01.x, r01.x); ffma2(a1, h01.y, r01.y);
            ffma2(a2, h23.x, r23.x); ffma2(a3, h23.y, r23.y);
        }
        float2 f0 = u2f2(a0), f1 = u2f2(a1), f2 = u2f2(a2), f3 = u2f2(a3);
        float sum = ((f0.x + f0.y) + (f1.x + f1.y)) +
                    ((f2.x + f2.y) + (f3.x + f3.y));

        float uv = __ldg(u + (ll)(b0 + b) * uSB + (ll)c * uSC + col0 + j);
        float val = sum + uv;
        ll eoff = (ll)(b0 + b) * UDIM + col0 + j;
        g[(ll)(c + 1) * gStep + eoff] = val;
        {
            u16 hh, lw;
            bsplit(val, hh, lw);
            ll gco = (ll)(c + 1) * gcStep + eoff;
            GCh[gco] = hh; GCl[gco] = lw;
        }

        __threadfence();
        __syncthreads();
        if (tid == 0) {
            unsigned arrived = atomicAdd((unsigned*)&g_bar[c], 1u) + 1u;
            if (arrived < P) {
                while (g_bar[c] < P) { }
            }
            __threadfence();
        }
        __syncthreads();
    }
}

// ---------------------------------------------------------------------------
extern "C" void kernel_launch(void* const* d_in, const int* in_sizes, int n_in,
                              void* d_out, int out_size)
{
    const float* x    = (const float*)d_in[0];
    const float* h0   = (const float*)d_in[1];
    const float* cst  = (const float*)d_in[2];
    const float* kern = (const float*)d_in[3];
    const float* rker = (const float*)d_in[4];
    float* out = (float*)d_out;

    const ll TU = (ll)TDIM * UDIM;
    const ll CU = (ll)CH * UDIM;
    const ll SL = (ll)SLE;
    const ll GB = (ll)BATCH * UDIM;
    const ll NAT_B = 1024, NAT_C = 32768;

    u16 *Xhi, *Xlo, *UAhi, *UAlo, *UBhi, *UBlo, *KThi, *KTlo;
    u16 *SPhi, *SPlo, *RPhi, *RPlo, *S32hi, *S32lo, *S64hi, *S64lo;
    u16 *C1hi, *C1lo, *C2hi, *C2lo, *GChi, *GClo;
    float *W8F, *sP1, *sP2, *sP3, *gbuf;
    cudaGetSymbolAddress((void**)&Xhi, g_Xhi);   cudaGetSymbolAddress((void**)&Xlo, g_Xlo);
    cudaGetSymbolAddress((void**)&UAhi, g_UAhi); cudaGetSymbolAddress((void**)&UAlo, g_UAlo);
    cudaGetSymbolAddress((void**)&UBhi, g_UBhi); cudaGetSymbolAddress((void**)&UBlo, g_UBlo);
    cudaGetSymbolAddress((void**)&KThi, g_KThi); cudaGetSymbolAddress((void**)&KTlo, g_KTlo);
    cudaGetSymbolAddress((void**)&SPhi, g_SPhi); cudaGetSymbolAddress((void**)&SPlo, g_SPlo);
    cudaGetSymbolAddress((void**)&RPhi, g_RPhi); cudaGetSymbolAddress((void**)&RPlo, g_RPlo);
    cudaGetSymbolAddress((void**)&S32hi, g_S32hi); cudaGetSymbolAddress((void**)&S32lo, g_S32lo);
    cudaGetSymbolAddress((void**)&S64hi, g_S64hi); cudaGetSymbolAddress((void**)&S64lo, g_S64lo);
    cudaGetSymbolAddress((void**)&C1hi, g_C1hi); cudaGetSymbolAddress((void**)&C1lo, g_C1lo);
    cudaGetSymbolAddress((void**)&C2hi, g_C2hi); cudaGetSymbolAddress((void**)&C2lo, g_C2lo);
    cudaGetSymbolAddress((void**)&GChi, g_GChi); cudaGetSymbolAddress((void**)&GClo, g_GClo);
    cudaGetSymbolAddress((void**)&W8F, g_W8F);
    cudaGetSymbolAddress((void**)&sP1, g_sP1);
    cudaGetSymbolAddress((void**)&sP2, g_sP2);
    cudaGetSymbolAddress((void**)&sP3, g_sP3);
    cudaGetSymbolAddress((void**)&gbuf, g_gbuf);

    cudaFuncSetAttribute(tgemm_kernel,
        cudaFuncAttributeMaxDynamicSharedMemorySize, TG_SMEM);
    cudaFuncSetAttribute(phase2_kernel,
        cudaFuncAttributeMaxDynamicSharedMemorySize, P2_SMEM_FLOATS * 4);

    // ---- streams + events (created once; capture-safe fork/join) ----
    static cudaStream_t s2 = 0, s3 = 0;
    static cudaEvent_t evFork = 0, evX = 0, evS1 = 0, evPow = 0;
    static cudaEvent_t evP0[CH];
    static bool tried = false;
    if (!tried) {
        tried = true;
        if (cudaStreamCreateWithFlags(&s2, cudaStreamNonBlocking) != cudaSuccess)
            s2 = 0;
        if (cudaStreamCreateWithFlags(&s3, cudaStreamNonBlocking) != cudaSuccess)
            s3 = 0;
        cudaEventCreateWithFlags(&evFork, cudaEventDisableTiming);
        cudaEventCreateWithFlags(&evX,    cudaEventDisableTiming);
        cudaEventCreateWithFlags(&evS1,   cudaEventDisableTiming);
        cudaEventCreateWithFlags(&evPow,  cudaEventDisableTiming);
        for (int i = 0; i < CH; i++)
            cudaEventCreateWithFlags(&evP0[i], cudaEventDisableTiming);
    }

    cudaEventRecord(evFork, 0);
    cudaStreamWaitEvent(s2, evFork, 0);
    cudaStreamWaitEvent(s3, evFork, 0);

    // ======== s3: R-derived prep + full power chain ========
    bar_reset_kernel<<<(MAX_BAR + 255) / 256, 256, 0, s3>>>();
    transpose_split_kernel<<<dim3(32, 32), 256, 0, s3>>>(rker, SPhi, SPlo);    // S^1
    cudaEventRecord(evS1, s3);
    split_gather_kernel<<<UDIM, 256, 0, s3>>>(rker, NAT_B, NAT_C, RPhi, RPlo); // R^1
    copy_h0_kernel<<<(BATCH * UDIM + 255) / 256, 256, 0, s3>>>(h0, gbuf, GChi, GClo);
    {
        dim3 g1(8, 8), g2(8, 16), g4(8, 32), g8(8, 64);
        tgemm_kernel<<<g1, 256, TG_SMEM, s3>>>(SPhi, SPlo, NAT_B, NAT_C, RPhi, RPlo,
            nullptr, 0, 0, nullptr, 0, 0, SPhi + SL, SPlo + SL, NAT_B, NAT_C);      // S^2
        tgemm_kernel<<<g1, 256, TG_SMEM, s3>>>(RPhi, RPlo, NAT_B, NAT_C, SPhi, SPlo,
            nullptr, 0, 0, nullptr, 0, 0, RPhi + SL, RPlo + SL, NAT_B, NAT_C);      // R^2
        tgemm_kernel<<<g2, 256, TG_SMEM, s3>>>(SPhi, SPlo, NAT_B, NAT_C,
            RPhi + SL, RPlo + SL,
            nullptr, 0, 0, nullptr, 0, 0, SPhi + 2 * SL, SPlo + 2 * SL, NAT_B, NAT_C); // S^3,4
        tgemm_kernel<<<g1, 256, TG_SMEM, s3>>>(RPhi + SL, RPlo + SL, NAT_B, NAT_C,
            SPhi + SL, SPlo + SL,
            nullptr, 0, 0, nullptr, 0, 0, RPhi + 2 * SL, RPlo + 2 * SL, NAT_B, NAT_C); // R^4
        tgemm_kernel<<<g4, 256, TG_SMEM, s3>>>(SPhi, SPlo, NAT_B, NAT_C,
            RPhi + 2 * SL, RPlo + 2 * SL,
            nullptr, 0, 0, nullptr, 0, 0, SPhi + 4 * SL, SPlo + 4 * SL, NAT_B, NAT_C); // S^5..8
        tgemm_kernel<<<g1, 256, TG_SMEM, s3>>>(RPhi + 2 * SL, RPlo + 2 * SL, NAT_B, NAT_C,
            SPhi + 3 * SL, SPlo + 3 * SL,
            nullptr, 0, 0, nullptr, 0, 0, RPhi + 3 * SL, RPlo + 3 * SL, NAT_B, NAT_C); // R^8
        tgemm_kernel<<<g8, 256, TG_SMEM, s3>>>(SPhi, SPlo, NAT_B, NAT_C,
            RPhi + 3 * SL, RPlo + 3 * SL,
            nullptr, 0, 0, nullptr, 0, 0, SPhi + 8 * SL, SPlo + 8 * SL, NAT_B, NAT_C); // S^9..16
        tgemm_kernel<<<g1, 256, TG_SMEM, s3>>>(RPhi + 3 * SL, RPlo + 3 * SL, NAT_B, NAT_C,
            SPhi + 7 * SL, SPlo + 7 * SL,
            nullptr, 0, 0, nullptr, 0, 0, RPhi + 4 * SL, RPlo + 4 * SL, NAT_B, NAT_C); // R^16
        tgemm_kernel<<<g1, 256, TG_SMEM, s3>>>(RPhi + 4 * SL, RPlo + 4 * SL, NAT_B, NAT_C,
            SPhi + 15 * SL, SPlo + 15 * SL,
            nullptr, 0, 0, nullptr, 0, 0, RPhi + 5 * SL, RPlo + 5 * SL, NAT_B, NAT_C); // R^32
        tgemm_kernel<<<g1, 256, TG_SMEM, s3>>>(SPhi + 15 * SL, SPlo + 15 * SL, NAT_B, NAT_C,
            RPhi + 4 * SL, RPlo + 4 * SL,
            nullptr, 0, 0, nullptr, 0, 0, S32hi, S32lo, NAT_B, NAT_C);               // S^32
        tgemm_kernel<<<g1, 256, TG_SMEM, s3>>>(RPhi + 5 * SL, RPlo + 5 * SL, NAT_B, NAT_C,
            S32hi, S32lo,
            nullptr, 0, 0, nullptr, 0, 0, RPhi + 6 * SL, RPlo + 6 * SL, NAT_B, NAT_C); // R^64
        tgemm_kernel<<<g1, 256, TG_SMEM, s3>>>(S32hi, S32lo, NAT_B, NAT_C,
            RPhi + 5 * SL, RPlo + 5 * SL,
            nullptr, 0, 0, nullptr, 0, 0, S64hi, S64lo, NAT_B, NAT_C);               // S^64
        tgemm_kernel<<<g1, 256, TG_SMEM, s3>>>(S64hi, S64lo, NAT_B, NAT_C,
            RPhi + 6 * SL, RPlo + 6 * SL,
            nullptr, 0, 0, W8F, NAT_B, NAT_C, nullptr, nullptr, 0, 0);               // S^128 fp32
    }
    cudaEventRecord(evPow, s3);

    // ======== main: x prep ========
    transpose_split_kernel<<<dim3(32, 32), 256>>>(kern, KThi, KTlo);
    split_gather_kernel<<<BATCH * TDIM, 256>>>(x, NAT_B, NAT_C, Xhi, Xlo);
    cudaEventRecord(evX, 0);
    cudaStreamWaitEvent(s2, evX, 0);

    // ======== s2: phase 0 as 16 sub-GEMMs by t mod 16 ========
    {
        dim3 gp(8, 32);   // M = 4096
        for (int j = 0; j < CH; j++) {
            tgemm_kernel<<<gp, 256, TG_SMEM, s2>>>(
                Xhi + (ll)j * 1024, Xlo + (ll)j * 1024, (ll)2048 * 1024, (ll)16 * 1024,
                KThi, KTlo,
                cst, 1024, 0,
                out + (ll)j * 1024, TU, CU,
                (j == 0) ? UAhi : nullptr, (j == 0) ? UAlo : nullptr, NAT_B, NAT_C);
            cudaEventRecord(evP0[j], s2);
        }
    }

    // ======== main: phase 1 Horner chain ========
    cudaStreamWaitEvent(0, evS1, 0);
    cudaStreamWaitEvent(0, evP0[0], 0);
    {
        dim3 gp(8, 32);   // M = 4096
        for (int jj = 1; jj < CH; jj++) {
            const u16* ah = (jj & 1) ? UAhi : UBhi;
            const u16* al = (jj & 1) ? UAlo : UBlo;
            u16* oh = (jj & 1) ? UBhi : UAhi;
            u16* ol = (jj & 1) ? UBlo : UAlo;
            cudaStreamWaitEvent(0, evP0[jj], 0);
            tgemm_kernel<<<gp, 256, TG_SMEM>>>(ah, al, NAT_B, NAT_C,
                SPhi, SPlo,
                out + (ll)jj * 1024, TU, CU,
                out + (ll)jj * 1024, TU, CU,
                oh, ol, NAT_B, NAT_C);
        }
    }

    cudaStreamWaitEvent(0, evPow, 0);

    // ---- radix-8 carry reduction: W = R^16 ----
    const float* sBase = out + (ll)(CH - 1) * 1024;

    tgemm_kernel<<<dim3(8, 16), 256, TG_SMEM>>>(UBhi, UBlo, NAT_B, 2 * NAT_C,
        SPhi + 15 * SL, SPlo + 15 * SL,
        sBase + CU, TU, 2 * CU,
        sP1, NAT_B, NAT_C,
        C1hi, C1lo, NAT_B, NAT_C);                                   // combine1
    tgemm_kernel<<<dim3(8, 8), 256, TG_SMEM>>>(C1hi, C1lo, NAT_B, 2 * NAT_C,
        S32hi, S32lo,
        sP1 + NAT_C, NAT_B, 2 * NAT_C,
        sP2, NAT_B, NAT_C,
        C2hi, C2lo, NAT_B, NAT_C);                                   // combine2
    tgemm_kernel<<<dim3(8, 4), 256, TG_SMEM>>>(C2hi, C2lo, NAT_B, 2 * NAT_C,
        S64hi, S64lo,
        sP2 + NAT_C, NAT_B, 2 * NAT_C,
        sP3, NAT_B, NAT_C,
        nullptr, nullptr, 0, 0);                                     // combine3

    phase2_kernel<<<P2_CTAS, 256, P2_SMEM_FLOATS * 4>>>(
        W8F, sP3, NAT_B, NAT_C, gbuf, 8 * GB, GChi, GClo, 8 * NAT_C, 15);

    tgemm_kernel<<<dim3(8, 4), 256, TG_SMEM>>>(GChi, GClo, NAT_B, 8 * NAT_C,
        S64hi, S64lo,
        sP2, NAT_B, 2 * NAT_C,
        nullptr, 0, 0,
        GChi + 4 * NAT_C, GClo + 4 * NAT_C, NAT_B, 8 * NAT_C);       // backfill3
    tgemm_kernel<<<dim3(8, 8), 256, TG_SMEM>>>(GChi, GClo, NAT_B, 4 * NAT_C,
        S32hi, S32lo,
        sP1, NAT_B, 2 * NAT_C,
        nullptr, 0, 0,
        GChi + 2 * NAT_C, GClo + 2 * NAT_C, NAT_B, 4 * NAT_C);       // backfill2
    tgemm_kernel<<<dim3(8, 16), 256, TG_SMEM>>>(GChi, GClo, NAT_B, 2 * NAT_C,
        SPhi + 15 * SL, SPlo + 15 * SL,
        sBase, TU, 2 * CU,
        nullptr, 0, 0,
        GChi + NAT_C, GClo + NAT_C, NAT_B, 2 * NAT_C);               // backfill1

    // phase 3 (single GEMM): out_{c*16+j} += g_c @ R^{j+1} for all j at once.
    tgemm_kernel<<<dim3(128, 32), 256, TG_SMEM>>>(GChi, GClo, NAT_B, NAT_C,
        SPhi, SPlo,
        out, TU, CU,
        out, TU, CU,
        nullptr, nullptr, 0, 0);
}

// round 13
// speedup vs baseline: 1.0495x; 1.0495x over previous
#include <cuda_runtime.h>
#include <cuda_bf16.h>
#include <cstdint>

typedef unsigned long long ull;
typedef long long ll;
typedef unsigned short u16;
typedef unsigned int u32;

#define UDIM 1024
#define BATCH 32
#define TDIM 2048
#define CH 16
#define NCH (TDIM / CH)          // 128
#define KTOT 3072
#define SLE (1024 * 1024)

// ---------------- scratch (device globals; no runtime alloc) ----------------
__device__ u16   g_Xhi[(size_t)BATCH * TDIM * UDIM];
__device__ u16   g_Xlo[(size_t)BATCH * TDIM * UDIM];
__device__ u16   g_UAhi[NCH * BATCH * UDIM], g_UAlo[NCH * BATCH * UDIM];
__device__ u16   g_UBhi[NCH * BATCH * UDIM], g_UBlo[NCH * BATCH * UDIM];
__device__ u16   g_KThi[SLE], g_KTlo[SLE];
__device__ u16   g_SPhi[CH * SLE], g_SPlo[CH * SLE];    // S^1..S^16
__device__ u16   g_S32hi[SLE], g_S32lo[SLE];            // S^32
__device__ u16   g_S64hi[SLE], g_S64lo[SLE];            // S^64
__device__ u16   g_RPhi[7 * SLE], g_RPlo[7 * SLE];      // R^1,2,4,8,16,32,64
__device__ u16   g_C1hi[64 * BATCH * UDIM], g_C1lo[64 * BATCH * UDIM];
__device__ u16   g_C2hi[32 * BATCH * UDIM], g_C2lo[32 * BATCH * UDIM];
__device__ u16   g_GChi[NCH * BATCH * UDIM], g_GClo[NCH * BATCH * UDIM];
__device__ float g_W8F[SLE];                // S^128 fp32 (serial chain weight)
__device__ float g_sP1[64 * BATCH * UDIM];
__device__ float g_sP2[32 * BATCH * UDIM];
__device__ float g_sP3[16 * BATCH * UDIM];
__device__ float g_sEv[64 * BATCH * UDIM];  // snapshot of even-chunk s_{2d}
__device__ float g_gbuf[NCH * BATCH * UDIM];

#define MAX_BAR 2048
__device__ volatile unsigned g_bar[MAX_BAR];

__global__ void __launch_bounds__(256) bar_reset_kernel() {
    int i = blockIdx.x * blockDim.x + threadIdx.x;
    if (i < MAX_BAR) *(unsigned*)&g_bar[i] = 0u;
}

// ---------------- helpers ----------------
__device__ __forceinline__ u32 smem_u32(const void* p) {
    u32 a;
    asm("{ .reg .u64 t; cvta.to.shared.u64 t, %1; cvt.u32.u64 %0, t; }"
        : "=r"(a) : "l"(p));
    return a;
}
#define SWZ(o) ((o) ^ (((o) >> 3) & 0x70))

__device__ __forceinline__ void bsplit(float v, u16& h, u16& l) {
    __nv_bfloat16 bh = __float2bfloat16_rn(v);
    float r = v - __bfloat162float(bh);
    __nv_bfloat16 bl = __float2bfloat16_rn(r);
    h = __bfloat16_as_ushort(bh);
    l = __bfloat16_as_ushort(bl);
}

__global__ void __launch_bounds__(256) copy_h0_kernel(
    const float* __restrict__ h0, float* __restrict__ g,
    u16* __restrict__ GCh, u16* __restrict__ GCl)
{
    int i = blockIdx.x * blockDim.x + threadIdx.x;
    if (i < BATCH * UDIM) {
        float v = h0[i];
        g[i] = v;
        u16 h, l;
        bsplit(v, h, l);
        GCh[i] = h; GCl[i] = l;
    }
}

// fp32 strided-row copy (row m -> (m&31)*sB + (m>>5)*sC, dst likewise)
__global__ void __launch_bounds__(256) copy_rows_kernel(
    const float* __restrict__ src, ll sB, ll sC,
    float* __restrict__ dst, ll dB, ll dC)
{
    int m = blockIdx.x;
    int k = threadIdx.x * 4;
    ll soff = (ll)(m & 31) * sB + (ll)(m >> 5) * sC + k;
    ll doff = (ll)(m & 31) * dB + (ll)(m >> 5) * dC + k;
    *(float4*)(dst + doff) = *(const float4*)(src + soff);
}

__device__ __forceinline__ void ldsm4(u32 addr, u32& r0, u32& r1, u32& r2, u32& r3) {
    asm volatile("ldmatrix.sync.aligned.m8n8.x4.shared.b16 {%0,%1,%2,%3}, [%4];"
                 : "=r"(r0), "=r"(r1), "=r"(r2), "=r"(r3) : "r"(addr));
}
__device__ __forceinline__ void mma16816(float* d, const u32* a, const u32* b) {
    asm volatile(
        "mma.sync.aligned.m16n8k16.row.col.f32.bf16.bf16.f32 "
        "{%0,%1,%2,%3}, {%4,%5,%6,%7}, {%8,%9}, {%0,%1,%2,%3};"
        : "+f"(d[0]), "+f"(d[1]), "+f"(d[2]), "+f"(d[3])
        : "r"(a[0]), "r"(a[1]), "r"(a[2]), "r"(a[3]), "r"(b[0]), "r"(b[1]));
}

// ------ split_gather: fp32 strided rows -> bf16 hi/lo at strided out -------
__global__ void __launch_bounds__(256) split_gather_kernel(
    const float* __restrict__ src, ll sB, ll sC,
    u16* __restrict__ hi, u16* __restrict__ lo, ll dB, ll dC)
{
    int m = blockIdx.x;
    int k = threadIdx.x * 4;
    ll off = (ll)(m & 31) * sB + (ll)(m >> 5) * sC + k;
    float4 v = *(const float4*)(src + off);
    u16 h0, h1, h2, h3, l0, l1, l2, l3;
    bsplit(v.x, h0, l0); bsplit(v.y, h1, l1);
    bsplit(v.z, h2, l2); bsplit(v.w, h3, l3);
    ll doff = (ll)(m & 31) * dB + (ll)(m >> 5) * dC + k;
    *(ushort4*)(hi + doff) = make_ushort4(h0, h1, h2, h3);
    *(ushort4*)(lo + doff) = make_ushort4(l0, l1, l2, l3);
}

// ------------- transpose_split: fp32 W[k][n] -> bf16 hi/lo of W^T [n][k] ----
__global__ void __launch_bounds__(256) transpose_split_kernel(
    const float* __restrict__ src, u16* __restrict__ thi, u16* __restrict__ tlo)
{
    __shared__ float tile[32][33];
    int bx = blockIdx.x * 32;
    int by = blockIdx.y * 32;
    int tx = threadIdx.x & 31;
    int ty = threadIdx.x >> 5;
#pragma unroll
    for (int i = 0; i < 32; i += 8)
        tile[ty + i][tx] = src[(ll)(by + ty + i) * 1024 + bx + tx];
    __syncthreads();
#pragma unroll
    for (int i = 0; i < 32; i += 8) {
        u16 h, l;
        bsplit(tile[tx][ty + i], h, l);
        ll off = (ll)(bx + ty + i) * 1024 + (by + tx);
        thi[off] = h;
        tlo[off] = l;
    }
}

// ---------------------------------------------------------------------------
// tgemm (round-10 engine): C[m][n] = sum_k Af[m][k]*Bf[n][k], bf16 split,
// K'=3072 region select. CTA 128x128, BK=64, 3 stages, 2 CTAs/SM,
// 1 barrier/chunk. Row maps: (m&31)*SB+(m>>5)*SC for A/Add/OutF/OB.
// ---------------------------------------------------------------------------
#define TG_STAGE 32768
#define TG_SMEM (3 * TG_STAGE)
#define TG_NCHK (KTOT / 64)

__global__ void __launch_bounds__(256, 2) tgemm_kernel(
    const u16* __restrict__ Ahi, const u16* __restrict__ Alo, ll aSB, ll aSC,
    const u16* __restrict__ Bhi, const u16* __restrict__ Blo,
    const float* __restrict__ Add, ll adSB, ll adSC,
    float* __restrict__ OutF, ll ofSB, ll ofSC,
    u16* __restrict__ OBhi, u16* __restrict__ OBlo, ll obSB, ll obSC)
{
    extern __shared__ char smraw[];
    const u32 smbase = smem_u32(smraw);

    const int tid  = threadIdx.x;
    const int wid  = tid >> 5;
    const int lane = tid & 31;
    const ll mBase = (ll)blockIdx.y * 128;
    const ll nBase = (ll)blockIdx.x * 128;

    const int wm = (wid >> 1) * 32;
    const int wn = (wid & 1) * 64;

    float acc[2][8][4];
#pragma unroll
    for (int i = 0; i < 2; i++)
#pragma unroll
        for (int j = 0; j < 8; j++)
#pragma unroll
            for (int q = 0; q < 4; q++) acc[i][j][q] = 0.0f;

    auto load_chunk = [&](int c, int s) {
        const int reg = c >> 4;
        const u16* aptr = (reg == 1) ? Alo : Ahi;
        const u16* bptr = (reg == 2) ? Blo : Bhi;
        const ll kbase = (ll)(c & 15) * 64;
        u32 sa = smbase + (u32)s * TG_STAGE;
        u32 sb = sa + 16384;
#pragma unroll
        for (int i = 0; i < 4; i++) {
            int idx = i * 256 + tid;
            int row = idx >> 3;
            int cc  = (idx & 7) * 16;
            ll  kel = kbase + (idx & 7) * 8;
            ll  rm  = mBase + row;
            asm volatile("cp.async.cg.shared.global [%0], [%1], 16;"
                :: "r"(sa + SWZ((u32)(row * 128 + cc))),
                   "l"((ull)(uintptr_t)(aptr + (rm & 31) * aSB + (rm >> 5) * aSC + kel)));
            asm volatile("cp.async.cg.shared.global [%0], [%1], 16;"
                :: "r"(sb + SWZ((u32)(row * 128 + cc))),
                   "l"((ull)(uintptr_t)(bptr + (nBase + row) * 1024 + kel)));
        }
        asm volatile("cp.async.commit_group;" ::: "memory");
    };

    load_chunk(0, 0);
    load_chunk(1, 1);

    const int aRow = (lane & 15);
    const int aKb  = (lane >> 4) * 16;
    const int bRow = (lane & 7) + ((lane >> 4) << 3);
    const int bKb  = ((lane >> 3) & 1) * 16;

#pragma unroll 1
    for (int c = 0; c < TG_NCHK; c++) {
        if (c + 2 < TG_NCHK) {
            asm volatile("cp.async.wait_group 1;" ::: "memory");
        } else {
            asm volatile("cp.async.wait_group 0;" ::: "memory");
        }
        __syncthreads();
        if (c + 2 < TG_NCHK) load_chunk(c + 2, (c + 2) % 3);

        u32 sa = smbase + (u32)(c % 3) * TG_STAGE;
        u32 sb = sa + 16384;

#pragma unroll
        for (int k16 = 0; k16 < 4; k16++) {
            const int kb = k16 * 32;
            u32 areg[2][4];
#pragma unroll
            for (int i = 0; i < 2; i++) {
                u32 ad = sa + SWZ((u32)((wm + i * 16 + aRow) * 128 + kb + aKb));
                ldsm4(ad, areg[i][0], areg[i][1], areg[i][2], areg[i][3]);
            }
            u32 breg[4][4];
#pragma unroll
            for (int j16 = 0; j16 < 4; j16++) {
                u32 bd = sb + SWZ((u32)((wn + j16 * 16 + bRow) * 128 + kb + bKb));
                ldsm4(bd, breg[j16][0], breg[j16][1], breg[j16][2], breg[j16][3]);
            }
#pragma unroll
            for (int i = 0; i < 2; i++)
#pragma unroll
                for (int j = 0; j < 8; j++)
                    mma16816(acc[i][j], areg[i], &breg[j >> 1][(j & 1) * 2]);
        }
    }

    const int g  = lane >> 2;
    const int tg = (lane & 3) * 2;

#pragma unroll
    for (int i = 0; i < 2; i++) {
#pragma unroll
        for (int half = 0; half < 2; half++) {
            ll m = mBase + wm + i * 16 + g + half * 8;
            ll roff = (m & 31);
            ll coff = (m >> 5);
            const float* addp = Add ?
                Add + roff * adSB + coff * adSC + nBase : (const float*)0;
            float* ofp = OutF ?
                OutF + roff * ofSB + coff * ofSC + nBase : (float*)0;
            u16* obh = OBhi ? OBhi + roff * obSB + coff * obSC + nBase : (u16*)0;
            u16* obl = OBlo ? OBlo + roff * obSB + coff * obSC + nBase : (u16*)0;
#pragma unroll
            for (int j = 0; j < 8; j++) {
                int n = wn + j * 8 + tg;
                float v0 = acc[i][j][half * 2 + 0];
                float v1 = acc[i][j][half * 2 + 1];
                if (addp) {
                    float2 a = *(const float2*)(addp + n);
                    v0 += a.x; v1 += a.y;
                }
                if (ofp)
                    *(float2*)(ofp + n) = make_float2(v0, v1);
                if (obh) {
                    u16 h0, h1, l0, l1;
                    bsplit(v0, h0, l0);
                    bsplit(v1, h1, l1);
                    *(ushort2*)(obh + n) = make_ushort2(h0, h1);
                    *(ushort2*)(obl + n) = make_ushort2(l0, l1);
                }
            }
        }
    }
}

// ---------------------------------------------------------------------------
// phase2: serial carry chain G[c+1] = G[c] @ W + u[c]; emits bf16 split of
// each produced state into GC at stride gcStep.
// ---------------------------------------------------------------------------
__device__ __forceinline__ void ffma2(ull& d, ull a, ull b) {
    asm volatile("fma.rn.f32x2 %0, %1, %2, %0;" : "+l"(d) : "l"(a), "l"(b));
}
__device__ __forceinline__ float2 u2f2(ull v) {
    float2 f;
    f.x = __uint_as_float((unsigned)(v & 0xffffffffull));
    f.y = __uint_as_float((unsigned)(v >> 32));
    return f;
}
__device__ __forceinline__ float4 ldcg4(const float* p) {
    float4 v;
    asm volatile("ld.global.cg.v4.f32 {%0,%1,%2,%3}, [%4];"
                 : "=f"(v.x), "=f"(v.y), "=f"(v.z), "=f"(v.w) : "l"(p));
    return v;
}
#define P2_RPAD 1028
#define P2_HPAD 1032
#define P2_HS_OFF (32 * P2_RPAD)
#define P2_SMEM_FLOATS (32 * P2_RPAD + 8 * P2_HPAD)
#define P2_CTAS 128

__global__ void __launch_bounds__(256) phase2_kernel(
    const float* __restrict__ ST,
    const float* __restrict__ u, ll uSB, ll uSC,
    float* __restrict__ g, ll gStep,
    u16* __restrict__ GCh, u16* __restrict__ GCl, ll gcStep,
    int steps)
{
    extern __shared__ float sm[];
    const int tid = threadIdx.x;
    const int col0 = (blockIdx.x & 31) * 32;
    const int b0   = (blockIdx.x >> 5) * 8;

    for (int idx = tid; idx < 32 * 1024; idx += 256) {
        int j = idx >> 10, k = idx & 1023;
        sm[j * P2_RPAD + k] = ST[(size_t)(col0 + j) * 1024 + k];
    }
    __syncthreads();

    const int j = tid & 31;
    const int b = tid >> 5;
    const float* Rrow = &sm[j * P2_RPAD];
    const float* hrow = &sm[P2_HS_OFF + b * P2_HPAD];
    const unsigned P = gridDim.x;

    for (int c = 0; c < steps; c++) {
        const float* gsrc = g + (ll)c * gStep;
        for (int i = tid; i < 2048; i += 256) {
            int bb = i >> 8, kk = (i & 255) * 4;
            float4 v = ldcg4(gsrc + (size_t)(b0 + bb) * UDIM + kk);
            *(float4*)&sm[P2_HS_OFF + bb * P2_HPAD + kk] = v;
        }
        __syncthreads();

        ull a0 = 0, a1 = 0, a2 = 0, a3 = 0;
#pragma unroll 4
        for (int k = 0; k < 1024; k += 8) {
            ulonglong2 h01 = *(const ulonglong2*)(hrow + k);
            ulonglong2 h23 = *(const ulonglong2*)(hrow + k + 4);
            ulonglong2 r01 = *(const ulonglong2*)(Rrow + k);
            ulonglong2 r23 = *(const ulonglong2*)(Rrow + k + 4);
            ffma2(a0, h01.x, r01.x); ffma2(a1, h01.y, r01.y);
            ffma2(a2, h23.x, r23.x); ffma2(a3, h23.y, r23.y);
        }
        float2 f0 = u2f2(a0), f1 = u2f2(a1), f2 = u2f2(a2), f3 = u2f2(a3);
        float sum = ((f0.x + f0.y) + (f1.x + f1.y)) +
                    ((f2.x + f2.y) + (f3.x + f3.y));

        float uv = __ldg(u + (ll)(b0 + b) * uSB + (ll)c * uSC + col0 + j);
        float val = sum + uv;
        ll eoff = (ll)(b0 + b) * UDIM + col0 + j;
        g[(ll)(c + 1) * gStep + eoff] = val;
        {
            u16 hh, lw;
            bsplit(val, hh, lw);
            ll gco = (ll)(c + 1) * gcStep + eoff;
            GCh[gco] = hh; GCl[gco] = lw;
        }

        __threadfence();
        __syncthreads();
        if (tid == 0) {
            unsigned arrived = atomicAdd((unsigned*)&g_bar[c], 1u) + 1u;
            if (arrived < P) {
                while (g_bar[c] < P) { }
            }
            __threadfence();
        }
        __syncthreads();
    }
}

// ---------------------------------------------------------------------------
extern "C" void kernel_launch(void* const* d_in, const int* in_sizes, int n_in,
                              void* d_out, int out_size)
{
    const float* x    = (const float*)d_in[0];
    const float* h0   = (const float*)d_in[1];
    const float* cst  = (const float*)d_in[2];
    const float* kern = (const float*)d_in[3];
    const float* rker = (const float*)d_in[4];
    float* out = (float*)d_out;

    const ll TU = (ll)TDIM * UDIM;
    const ll CU = (ll)CH * UDIM;
    const ll SL = (ll)SLE;
    const ll GB = (ll)BATCH * UDIM;
    const ll NAT_B = 1024, NAT_C = 32768;

    u16 *Xhi, *Xlo, *UAhi, *UAlo, *UBhi, *UBlo, *KThi, *KTlo;
    u16 *SPhi, *SPlo, *RPhi, *RPlo, *S32hi, *S32lo, *S64hi, *S64lo;
    u16 *C1hi, *C1lo, *C2hi, *C2lo, *GChi, *GClo;
    float *W8F, *sP1, *sP2, *sP3, *sEv, *gbuf;
    cudaGetSymbolAddress((void**)&Xhi, g_Xhi);   cudaGetSymbolAddress((void**)&Xlo, g_Xlo);
    cudaGetSymbolAddress((void**)&UAhi, g_UAhi); cudaGetSymbolAddress((void**)&UAlo, g_UAlo);
    cudaGetSymbolAddress((void**)&UBhi, g_UBhi); cudaGetSymbolAddress((void**)&UBlo, g_UBlo);
    cudaGetSymbolAddress((void**)&KThi, g_KThi); cudaGetSymbolAddress((void**)&KTlo, g_KTlo);
    cudaGetSymbolAddress((void**)&SPhi, g_SPhi); cudaGetSymbolAddress((void**)&SPlo, g_SPlo);
    cudaGetSymbolAddress((void**)&RPhi, g_RPhi); cudaGetSymbolAddress((void**)&RPlo, g_RPlo);
    cudaGetSymbolAddress((void**)&S32hi, g_S32hi); cudaGetSymbolAddress((void**)&S32lo, g_S32lo);
    cudaGetSymbolAddress((void**)&S64hi, g_S64hi); cudaGetSymbolAddress((void**)&S64lo, g_S64lo);
    cudaGetSymbolAddress((void**)&C1hi, g_C1hi); cudaGetSymbolAddress((void**)&C1lo, g_C1lo);
    cudaGetSymbolAddress((void**)&C2hi, g_C2hi); cudaGetSymbolAddress((void**)&C2lo, g_C2lo);
    cudaGetSymbolAddress((void**)&GChi, g_GChi); cudaGetSymbolAddress((void**)&GClo, g_GClo);
    cudaGetSymbolAddress((void**)&W8F, g_W8F);
    cudaGetSymbolAddress((void**)&sP1, g_sP1);
    cudaGetSymbolAddress((void**)&sP2, g_sP2);
    cudaGetSymbolAddress((void**)&sP3, g_sP3);
    cudaGetSymbolAddress((void**)&sEv, g_sEv);
    cudaGetSymbolAddress((void**)&gbuf, g_gbuf);

    cudaFuncSetAttribute(tgemm_kernel,
        cudaFuncAttributeMaxDynamicSharedMemorySize, TG_SMEM);
    cudaFuncSetAttribute(phase2_kernel,
        cudaFuncAttributeMaxDynamicSharedMemorySize, P2_SMEM_FLOATS * 4);

    // ---- streams + events (created once; capture-safe fork/join) ----
    static cudaStream_t s2 = 0, s3 = 0;
    static cudaEvent_t evFork = 0, evKT = 0, evS1 = 0, evPow = 0;
    static cudaEvent_t evChain = 0, evB3 = 0, evB2 = 0, evB1 = 0, evP3 = 0;
    static cudaEvent_t evXs[CH], evP0[CH];
    static bool tried = false;
    if (!tried) {
        tried = true;
        if (cudaStreamCreateWithFlags(&s2, cudaStreamNonBlocking) != cudaSuccess)
            s2 = 0;
        if (cudaStreamCreateWithFlags(&s3, cudaStreamNonBlocking) != cudaSuccess)
            s3 = 0;
        cudaEventCreateWithFlags(&evFork, cudaEventDisableTiming);
        cudaEventCreateWithFlags(&evKT,   cudaEventDisableTiming);
        cudaEventCreateWithFlags(&evS1,   cudaEventDisableTiming);
        cudaEventCreateWithFlags(&evPow,  cudaEventDisableTiming);
        cudaEventCreateWithFlags(&evChain, cudaEventDisableTiming);
        cudaEventCreateWithFlags(&evB3,   cudaEventDisableTiming);
        cudaEventCreateWithFlags(&evB2,   cudaEventDisableTiming);
        cudaEventCreateWithFlags(&evB1,   cudaEventDisableTiming);
        cudaEventCreateWithFlags(&evP3,   cudaEventDisableTiming);
        for (int i = 0; i < CH; i++) {
            cudaEventCreateWithFlags(&evXs[i], cudaEventDisableTiming);
            cudaEventCreateWithFlags(&evP0[i], cudaEventDisableTiming);
        }
    }

    cudaEventRecord(evFork, 0);
    cudaStreamWaitEvent(s2, evFork, 0);
    cudaStreamWaitEvent(s3, evFork, 0);

    // ======== s3: R-derived prep + full power chain ========
    bar_reset_kernel<<<(MAX_BAR + 255) / 256, 256, 0, s3>>>();
    transpose_split_kernel<<<dim3(32, 32), 256, 0, s3>>>(rker, SPhi, SPlo);    // S^1
    cudaEventRecord(evS1, s3);
    split_gather_kernel<<<UDIM, 256, 0, s3>>>(rker, NAT_B, NAT_C,
        RPhi, RPlo, NAT_B, NAT_C);                                             // R^1
    copy_h0_kernel<<<(BATCH * UDIM + 255) / 256, 256, 0, s3>>>(h0, gbuf, GChi, GClo);
    {
        dim3 g1(8, 8), g2(8, 16), g4(8, 32), g8(8, 64);
        tgemm_kernel<<<g1, 256, TG_SMEM, s3>>>(SPhi, SPlo, NAT_B, NAT_C, RPhi, RPlo,
            nullptr, 0, 0, nullptr, 0, 0, SPhi + SL, SPlo + SL, NAT_B, NAT_C);      // S^2
        tgemm_kernel<<<g1, 256, TG_SMEM, s3>>>(RPhi, RPlo, NAT_B, NAT_C, SPhi, SPlo,
            nullptr, 0, 0, nullptr, 0, 0, RPhi + SL, RPlo + SL, NAT_B, NAT_C);      // R^2
        tgemm_kernel<<<g2, 256, TG_SMEM, s3>>>(SPhi, SPlo, NAT_B, NAT_C,
            RPhi + SL, RPlo + SL,
            nullptr, 0, 0, nullptr, 0, 0, SPhi + 2 * SL, SPlo + 2 * SL, NAT_B, NAT_C); // S^3,4
        tgemm_kernel<<<g1, 256, TG_SMEM, s3>>>(RPhi + SL, RPlo + SL, NAT_B, NAT_C,
            SPhi + SL, SPlo + SL,
            nullptr, 0, 0, nullptr, 0, 0, RPhi + 2 * SL, RPlo + 2 * SL, NAT_B, NAT_C); // R^4
        tgemm_kernel<<<g4, 256, TG_SMEM, s3>>>(SPhi, SPlo, NAT_B, NAT_C,
            RPhi + 2 * SL, RPlo + 2 * SL,
            nullptr, 0, 0, nullptr, 0, 0, SPhi + 4 * SL, SPlo + 4 * SL, NAT_B, NAT_C); // S^5..8
        tgemm_kernel<<<g1, 256, TG_SMEM, s3>>>(RPhi + 2 * SL, RPlo + 2 * SL, NAT_B, NAT_C,
            SPhi + 3 * SL, SPlo + 3 * SL,
            nullptr, 0, 0, nullptr, 0, 0, RPhi + 3 * SL, RPlo + 3 * SL, NAT_B, NAT_C); // R^8
        tgemm_kernel<<<g8, 256, TG_SMEM, s3>>>(SPhi, SPlo, NAT_B, NAT_C,
            RPhi + 3 * SL, RPlo + 3 * SL,
            nullptr, 0, 0, nullptr, 0, 0, SPhi + 8 * SL, SPlo + 8 * SL, NAT_B, NAT_C); // S^9..16
        tgemm_kernel<<<g1, 256, TG_SMEM, s3>>>(RPhi + 3 * SL, RPlo + 3 * SL, NAT_B, NAT_C,
            SPhi + 7 * SL, SPlo + 7 * SL,
            nullptr, 0, 0, nullptr, 0, 0, RPhi + 4 * SL, RPlo + 4 * SL, NAT_B, NAT_C); // R^16
        tgemm_kernel<<<g1, 256, TG_SMEM, s3>>>(RPhi + 4 * SL, RPlo + 4 * SL, NAT_B, NAT_C,
            SPhi + 15 * SL, SPlo + 15 * SL,
            nullptr, 0, 0, nullptr, 0, 0, RPhi + 5 * SL, RPlo + 5 * SL, NAT_B, NAT_C); // R^32
        tgemm_kernel<<<g1, 256, TG_SMEM, s3>>>(SPhi + 15 * SL, SPlo + 15 * SL, NAT_B, NAT_C,
            RPhi + 4 * SL, RPlo + 4 * SL,
            nullptr, 0, 0, nullptr, 0, 0, S32hi, S32lo, NAT_B, NAT_C);               // S^32
        tgemm_kernel<<<g1, 256, TG_SMEM, s3>>>(RPhi + 5 * SL, RPlo + 5 * SL, NAT_B, NAT_C,
            S32hi, S32lo,
            nullptr, 0, 0, nullptr, 0, 0, RPhi + 6 * SL, RPlo + 6 * SL, NAT_B, NAT_C); // R^64
        tgemm_kernel<<<g1, 256, TG_SMEM, s3>>>(S32hi, S32lo, NAT_B, NAT_C,
            RPhi + 5 * SL, RPlo + 5 * SL,
            nullptr, 0, 0, nullptr, 0, 0, S64hi, S64lo, NAT_B, NAT_C);               // S^64
        tgemm_kernel<<<g1, 256, TG_SMEM, s3>>>(S64hi, S64lo, NAT_B, NAT_C,
            RPhi + 6 * SL, RPlo + 6 * SL,
            nullptr, 0, 0, W8F, NAT_B, NAT_C, nullptr, nullptr, 0, 0);               // S^128 fp32
    }
    cudaEventRecord(evPow, s3);

    // ======== main: K^T, then x split sliced by t mod 16 ========
    transpose_split_kernel<<<dim3(32, 32), 256>>>(kern, KThi, KTlo);
    cudaEventRecord(evKT, 0);
    cudaStreamWaitEvent(s2, evKT, 0);
    for (int j = 0; j < CH; j++) {
        split_gather_kernel<<<NCH * BATCH, 256>>>(x + (ll)j * 1024, TU, (ll)16 * 1024,
            Xhi + (ll)j * 1024, Xlo + (ll)j * 1024, TU, (ll)16 * 1024);
        cudaEventRecord(evXs[j], 0);
        cudaStreamWaitEvent(s2, evXs[j], 0);
        dim3 gp(8, 32);
        tgemm_kernel<<<gp, 256, TG_SMEM, s2>>>(
            Xhi + (ll)j * 1024, Xlo + (ll)j * 1024, TU, (ll)16 * 1024,
            KThi, KTlo,
            cst, 1024, 0,
            out + (ll)j * 1024, TU, CU,
            (j == 0) ? UAhi : nullptr, (j == 0) ? UAlo : nullptr, NAT_B, NAT_C);
        cudaEventRecord(evP0[j], s2);
    }

    // ======== main: phase 1 Horner chain ========
    cudaStreamWaitEvent(0, evS1, 0);
    cudaStreamWaitEvent(0, evP0[0], 0);
    {
        dim3 gp(8, 32);   // M = 4096
        for (int jj = 1; jj < CH; jj++) {
            const u16* ah = (jj & 1) ? UAhi : UBhi;
            const u16* al = (jj & 1) ? UAlo : UBlo;
            u16* oh = (jj & 1) ? UBhi : UAhi;
            u16* ol = (jj & 1) ? UBlo : UAlo;
            cudaStreamWaitEvent(0, evP0[jj], 0);
            tgemm_kernel<<<gp, 256, TG_SMEM>>>(ah, al, NAT_B, NAT_C,
                SPhi, SPlo,
                out + (ll)jj * 1024, TU, CU,
                out + (ll)jj * 1024, TU, CU,
                oh, ol, NAT_B, NAT_C);
        }
    }

    cudaStreamWaitEvent(0, evPow, 0);

    // ---- radix-8 carry reduction: W = R^16 ----
    const float* sBase = out + (ll)(CH - 1) * 1024;

    // Snapshot even-chunk s_{2d} fp32 (race fix: phase-3 residue kernels will
    // overwrite out rows j=15 of even chunks while backfill1 still needs them).
    copy_rows_kernel<<<2048, 256>>>(sBase, TU, 2 * CU, sEv, NAT_B, NAT_C);

    tgemm_kernel<<<dim3(8, 16), 256, TG_SMEM>>>(UBhi, UBlo, NAT_B, 2 * NAT_C,
        SPhi + 15 * SL, SPlo + 15 * SL,
        sBase + CU, TU, 2 * CU,
        sP1, NAT_B, NAT_C,
        C1hi, C1lo, NAT_B, NAT_C);                                   // combine1
    tgemm_kernel<<<dim3(8, 8), 256, TG_SMEM>>>(C1hi, C1lo, NAT_B, 2 * NAT_C,
        S32hi, S32lo,
        sP1 + NAT_C, NAT_B, 2 * NAT_C,
        sP2, NAT_B, NAT_C,
        C2hi, C2lo, NAT_B, NAT_C);                                   // combine2
    tgemm_kernel<<<dim3(8, 4), 256, TG_SMEM>>>(C2hi, C2lo, NAT_B, 2 * NAT_C,
        S64hi, S64lo,
        sP2 + NAT_C, NAT_B, 2 * NAT_C,
        sP3, NAT_B, NAT_C,
        nullptr, nullptr, 0, 0);                                     // combine3

    phase2_kernel<<<P2_CTAS, 256, P2_SMEM_FLOATS * 4>>>(
        W8F, sP3, NAT_B, NAT_C, gbuf, 8 * GB, GChi, GClo, 8 * NAT_C, 15);
    cudaEventRecord(evChain, 0);

    // s2: phase3 residue c ≡ 0 (mod 8)  (M=512)
    cudaStreamWaitEvent(s2, evChain, 0);
    tgemm_kernel<<<dim3(128, 4), 256, TG_SMEM, s2>>>(GChi, GClo, NAT_B, 8 * NAT_C,
        SPhi, SPlo,
        out, TU, 8 * CU,
        out, TU, 8 * CU,
        nullptr, nullptr, 0, 0);

    tgemm_kernel<<<dim3(8, 4), 256, TG_SMEM>>>(GChi, GClo, NAT_B, 8 * NAT_C,
        S64hi, S64lo,
        sP2, NAT_B, 2 * NAT_C,
        nullptr, 0, 0,
        GChi + 4 * NAT_C, GClo + 4 * NAT_C, NAT_B, 8 * NAT_C);       // backfill3
    cudaEventRecord(evB3, 0);

    // s2: phase3 residue c ≡ 4 (mod 8)
    cudaStreamWaitEvent(s2, evB3, 0);
    tgemm_kernel<<<dim3(128, 4), 256, TG_SMEM, s2>>>(
        GChi + 4 * NAT_C, GClo + 4 * NAT_C, NAT_B, 8 * NAT_C,
        SPhi, SPlo,
        out + 4 * CU, TU, 8 * CU,
        out + 4 * CU, TU, 8 * CU,
        nullptr, nullptr, 0, 0);

    tgemm_kernel<<<dim3(8, 8), 256, TG_SMEM>>>(GChi, GClo, NAT_B, 4 * NAT_C,
        S32hi, S32lo,
        sP1, NAT_B, 2 * NAT_C,
        nullptr, 0, 0,
        GChi + 2 * NAT_C, GClo + 2 * NAT_C, NAT_B, 4 * NAT_C);       // backfill2
    cudaEventRecord(evB2, 0);

    // s2: phase3 residue c ≡ 2 (mod 4)  (M=1024)
    cudaStreamWaitEvent(s2, evB2, 0);
    tgemm_kernel<<<dim3(128, 8), 256, TG_SMEM, s2>>>(
        GChi + 2 * NAT_C, GClo + 2 * NAT_C, NAT_B, 4 * NAT_C,
        SPhi, SPlo,
        out + 2 * CU, TU, 4 * CU,
        out + 2 * CU, TU, 4 * CU,
        nullptr, nullptr, 0, 0);

    // backfill1 now reads the SNAPSHOT of even s (race-free)
    tgemm_kernel<<<dim3(8, 16), 256, TG_SMEM>>>(GChi, GClo, NAT_B, 2 * NAT_C,
        SPhi + 15 * SL, SPlo + 15 * SL,
        sEv, NAT_B, NAT_C,
        nullptr, 0, 0,
        GChi + NAT_C, GClo + NAT_C, NAT_B, 2 * NAT_C);               // backfill1
    cudaEventRecord(evB1, 0);

    // s2: phase3 odd residues (M=2048)
    cudaStreamWaitEvent(s2, evB1, 0);
    tgemm_kernel<<<dim3(128, 16), 256, TG_SMEM, s2>>>(
        GChi + NAT_C, GClo + NAT_C, NAT_B, 2 * NAT_C,
        SPhi, SPlo,
        out + CU, TU, 2 * CU,
        out + CU, TU, 2 * CU,
        nullptr, nullptr, 0, 0);

    // join s2 back into the capture stream
    cudaEventRecord(evP3, s2);
    cudaStreamWaitEvent(0, evP3, 0);
}

// round 14
// speedup vs baseline: 1.0527x; 1.0031x over previous
#include <cuda_runtime.h>
#include <cuda_bf16.h>
#include <cstdint>

typedef unsigned long long ull;
typedef long long ll;
typedef unsigned short u16;
typedef unsigned int u32;

#define UDIM 1024
#define BATCH 32
#define TDIM 2048
#define CH 16
#define NCH (TDIM / CH)          // 128
#define SLE (1024 * 1024)

// ---------------- scratch (device globals; no runtime alloc) ----------------
__device__ u16   g_Xhi[(size_t)BATCH * TDIM * UDIM];
__device__ u16   g_Xlo[(size_t)BATCH * TDIM * UDIM];
__device__ u16   g_UAhi[NCH * BATCH * UDIM], g_UAlo[NCH * BATCH * UDIM];
__device__ u16   g_UBhi[NCH * BATCH * UDIM], g_UBlo[NCH * BATCH * UDIM];
__device__ u16   g_KThi[SLE], g_KTlo[SLE];
__device__ u16   g_SPhi[CH * SLE], g_SPlo[CH * SLE];    // S^1..S^16
__device__ u16   g_S32hi[SLE], g_S32lo[SLE];            // S^32
__device__ u16   g_S64hi[SLE], g_S64lo[SLE];            // S^64
__device__ u16   g_RPhi[7 * SLE], g_RPlo[7 * SLE];      // R^1,2,4,8,16,32,64
__device__ u16   g_C1hi[64 * BATCH * UDIM], g_C1lo[64 * BATCH * UDIM];
__device__ u16   g_C2hi[32 * BATCH * UDIM], g_C2lo[32 * BATCH * UDIM];
__device__ u16   g_GChi[NCH * BATCH * UDIM], g_GClo[NCH * BATCH * UDIM];
__device__ float g_W8F[SLE];                // S^128 fp32 (serial chain weight)
__device__ float g_sP1[64 * BATCH * UDIM];
__device__ float g_sP2[32 * BATCH * UDIM];
__device__ float g_sP3[16 * BATCH * UDIM];
__device__ float g_sEv[64 * BATCH * UDIM];  // snapshot of even-chunk s_{2d}
__device__ float g_gbuf[NCH * BATCH * UDIM];

#define MAX_BAR 2048
__device__ volatile unsigned g_bar[MAX_BAR];

__global__ void __launch_bounds__(256) bar_reset_kernel() {
    int i = blockIdx.x * blockDim.x + threadIdx.x;
    if (i < MAX_BAR) *(unsigned*)&g_bar[i] = 0u;
}

// ---------------- helpers ----------------
__device__ __forceinline__ u32 smem_u32(const void* p) {
    u32 a;
    asm("{ .reg .u64 t; cvta.to.shared.u64 t, %1; cvt.u32.u64 %0, t; }"
        : "=r"(a) : "l"(p));
    return a;
}
#define SWZ64(o) ((o) ^ (((o) >> 3) & 0x30))

__device__ __forceinline__ void bsplit(float v, u16& h, u16& l) {
    __nv_bfloat16 bh = __float2bfloat16_rn(v);
    float r = v - __bfloat162float(bh);
    __nv_bfloat16 bl = __float2bfloat16_rn(r);
    h = __bfloat16_as_ushort(bh);
    l = __bfloat16_as_ushort(bl);
}

__global__ void __launch_bounds__(256) copy_h0_kernel(
    const float* __restrict__ h0, float* __restrict__ g,
    u16* __restrict__ GCh, u16* __restrict__ GCl)
{
    int i = blockIdx.x * blockDim.x + threadIdx.x;
    if (i < BATCH * UDIM) {
        float v = h0[i];
        g[i] = v;
        u16 h, l;
        bsplit(v, h, l);
        GCh[i] = h; GCl[i] = l;
    }
}

// fp32 strided-row copy (row m -> (m&31)*sB + (m>>5)*sC, dst likewise)
__global__ void __launch_bounds__(256) copy_rows_kernel(
    const float* __restrict__ src, ll sB, ll sC,
    float* __restrict__ dst, ll dB, ll dC)
{
    int m = blockIdx.x;
    int k = threadIdx.x * 4;
    ll soff = (ll)(m & 31) * sB + (ll)(m >> 5) * sC + k;
    ll doff = (ll)(m & 31) * dB + (ll)(m >> 5) * dC + k;
    *(float4*)(dst + doff) = *(const float4*)(src + soff);
}

__device__ __forceinline__ void ldsm4(u32 addr, u32& r0, u32& r1, u32& r2, u32& r3) {
    asm volatile("ldmatrix.sync.aligned.m8n8.x4.shared.b16 {%0,%1,%2,%3}, [%4];"
                 : "=r"(r0), "=r"(r1), "=r"(r2), "=r"(r3) : "r"(addr));
}
__device__ __forceinline__ void mma16816(float* d, const u32* a, const u32* b) {
    asm volatile(
        "mma.sync.aligned.m16n8k16.row.col.f32.bf16.bf16.f32 "
        "{%0,%1,%2,%3}, {%4,%5,%6,%7}, {%8,%9}, {%0,%1,%2,%3};"
        : "+f"(d[0]), "+f"(d[1]), "+f"(d[2]), "+f"(d[3])
        : "r"(a[0]), "r"(a[1]), "r"(a[2]), "r"(a[3]), "r"(b[0]), "r"(b[1]));
}

// ------ split_gather: fp32 strided rows -> bf16 hi/lo at strided out -------
__global__ void __launch_bounds__(256) split_gather_kernel(
    const float* __restrict__ src, ll sB, ll sC,
    u16* __restrict__ hi, u16* __restrict__ lo, ll dB, ll dC)
{
    int m = blockIdx.x;
    int k = threadIdx.x * 4;
    ll off = (ll)(m & 31) * sB + (ll)(m >> 5) * sC + k;
    float4 v = *(const float4*)(src + off);
    u16 h0, h1, h2, h3, l0, l1, l2, l3;
    bsplit(v.x, h0, l0); bsplit(v.y, h1, l1);
    bsplit(v.z, h2, l2); bsplit(v.w, h3, l3);
    ll doff = (ll)(m & 31) * dB + (ll)(m >> 5) * dC + k;
    *(ushort4*)(hi + doff) = make_ushort4(h0, h1, h2, h3);
    *(ushort4*)(lo + doff) = make_ushort4(l0, l1, l2, l3);
}

// ------------- transpose_split: fp32 W[k][n] -> bf16 hi/lo of W^T [n][k] ----
__global__ void __launch_bounds__(256) transpose_split_kernel(
    const float* __restrict__ src, u16* __restrict__ thi, u16* __restrict__ tlo)
{
    __shared__ float tile[32][33];
    int bx = blockIdx.x * 32;
    int by = blockIdx.y * 32;
    int tx = threadIdx.x & 31;
    int ty = threadIdx.x >> 5;
#pragma unroll
    for (int i = 0; i < 32; i += 8)
        tile[ty + i][tx] = src[(ll)(by + ty + i) * 1024 + bx + tx];
    __syncthreads();
#pragma unroll
    for (int i = 0; i < 32; i += 8) {
        u16 h, l;
        bsplit(tile[tx][ty + i], h, l);
        ll off = (ll)(bx + ty + i) * 1024 + (by + tx);
        thi[off] = h;
        tlo[off] = l;
    }
}

// ---------------------------------------------------------------------------
// tgemm (operand-shared, BK=32, 2 CTAs/SM): C[m][n] = sum_k Af[m][k]*Bf[n][k]
// via bf16 split. Each stage holds Ahi/Alo/Bhi/Blo 128x32 tiles (4 x 8KB,
// 64-byte rows, SW64 swizzle). Per k16 the 3 products (hi*hi, lo*hi, hi*lo)
// reuse resident tiles -> 1.5x less gmem/L2 traffic and ldsm than K'=3072
// region-select, at identical tensor-op count. 3 stages = 96KB -> 2 CTAs/SM.
// Product order keeps peak live regs under the 128-reg cap.
// Row maps: (m&31)*SB + (m>>5)*SC for A/Add/OutF/OB. B natural [n][k].
// ---------------------------------------------------------------------------
#define TG_STAGE 32768          // 4 x 8KB tiles
#define TG_SMEM (3 * TG_STAGE)  // 96KB
#define TG_NCHK 32              // K=1024 / 32

__global__ void __launch_bounds__(256, 2) tgemm_kernel(
    const u16* __restrict__ Ahi, const u16* __restrict__ Alo, ll aSB, ll aSC,
    const u16* __restrict__ Bhi, const u16* __restrict__ Blo,
    const float* __restrict__ Add, ll adSB, ll adSC,
    float* __restrict__ OutF, ll ofSB, ll ofSC,
    u16* __restrict__ OBhi, u16* __restrict__ OBlo, ll obSB, ll obSC)
{
    extern __shared__ char smraw[];
    const u32 smbase = smem_u32(smraw);

    const int tid  = threadIdx.x;
    const int wid  = tid >> 5;
    const int lane = tid & 31;
    const ll mBase = (ll)blockIdx.y * 128;
    const ll nBase = (ll)blockIdx.x * 128;

    const int wm = (wid >> 1) * 32;
    const int wn = (wid & 1) * 64;

    float acc[2][8][4];
#pragma unroll
    for (int i = 0; i < 2; i++)
#pragma unroll
        for (int j = 0; j < 8; j++)
#pragma unroll
            for (int q = 0; q < 4; q++) acc[i][j][q] = 0.0f;

    // per chunk: 4 tiles x 128 rows x 64B; 512 x 16B per tile; 2 iters/thread
    auto load_chunk = [&](int c, int s) {
        const ll kbase = (ll)c * 32;
        u32 base = smbase + (u32)s * TG_STAGE;
#pragma unroll
        for (int i = 0; i < 2; i++) {
            int idx = i * 256 + tid;         // 0..511
            int row = idx >> 2;              // 0..127
            int q   = (idx & 3) * 16;        // byte quad in 64B row
            u32 sw  = SWZ64((u32)(row * 64 + q));
            ll  kel = kbase + (idx & 3) * 8; // element offset
            ll  rm  = mBase + row;
            ll aoff = (rm & 31) * aSB + (rm >> 5) * aSC + kel;
            ll boff = (nBase + row) * 1024 + kel;
            asm volatile("cp.async.cg.shared.global [%0], [%1], 16;"
                :: "r"(base + sw), "l"((ull)(uintptr_t)(Ahi + aoff)));
            asm volatile("cp.async.cg.shared.global [%0], [%1], 16;"
                :: "r"(base + 8192 + sw), "l"((ull)(uintptr_t)(Alo + aoff)));
            asm volatile("cp.async.cg.shared.global [%0], [%1], 16;"
                :: "r"(base + 16384 + sw), "l"((ull)(uintptr_t)(Bhi + boff)));
            asm volatile("cp.async.cg.shared.global [%0], [%1], 16;"
                :: "r"(base + 24576 + sw), "l"((ull)(uintptr_t)(Blo + boff)));
        }
        asm volatile("cp.async.commit_group;" ::: "memory");
    };

    load_chunk(0, 0);
    load_chunk(1, 1);

    const int aRow = (lane & 15);
    const int aKb  = (lane >> 4) * 16;
    const int bRow = (lane & 7) + ((lane >> 4) << 3);
    const int bKb  = ((lane >> 3) & 1) * 16;

#pragma unroll 1
    for (int c = 0; c < TG_NCHK; c++) {
        if (c + 2 < TG_NCHK) {
            asm volatile("cp.async.wait_group 1;" ::: "memory");
        } else {
            asm volatile("cp.async.wait_group 0;" ::: "memory");
        }
        __syncthreads();
        if (c + 2 < TG_NCHK) load_chunk(c + 2, (c + 2) % 3);

        u32 base = smbase + (u32)(c % 3) * TG_STAGE;

#pragma unroll
        for (int k16 = 0; k16 < 2; k16++) {
            const int kb = k16 * 32;
            // hi*hi
            u32 ah[2][4];
#pragma unroll
            for (int i = 0; i < 2; i++) {
                u32 ad = base + SWZ64((u32)((wm + i * 16 + aRow) * 64 + kb + aKb));
                ldsm4(ad, ah[i][0], ah[i][1], ah[i][2], ah[i][3]);
            }
            u32 bh[4][4];
#pragma unroll
            for (int j16 = 0; j16 < 4; j16++) {
                u32 bd = base + 16384 +
                         SWZ64((u32)((wn + j16 * 16 + bRow) * 64 + kb + bKb));
                ldsm4(bd, bh[j16][0], bh[j16][1], bh[j16][2], bh[j16][3]);
            }
#pragma unroll
            for (int i = 0; i < 2; i++)
#pragma unroll
                for (int j = 0; j < 8; j++)
                    mma16816(acc[i][j], ah[i], &bh[j >> 1][(j & 1) * 2]);

            // lo*hi (al transient; bh reused then dead)
            {
                u32 al[2][4];
#pragma unroll
                for (int i = 0; i < 2; i++) {
                    u32 ad = base + 8192 +
                             SWZ64((u32)((wm + i * 16 + aRow) * 64 + kb + aKb));
                    ldsm4(ad, al[i][0], al[i][1], al[i][2], al[i][3]);
                }
#pragma unroll
                for (int i = 0; i < 2; i++)
#pragma unroll
                    for (int j = 0; j < 8; j++)
                        mma16816(acc[i][j], al[i], &bh[j >> 1][(j & 1) * 2]);
            }

            // hi*lo (bl loaded after bh dead; ah reused)
            {
                u32 bl[4][4];
#pragma unroll
                for (int j16 = 0; j16 < 4; j16++) {
                    u32 bd = base + 24576 +
                             SWZ64((u32)((wn + j16 * 16 + bRow) * 64 + kb + bKb));
                    ldsm4(bd, bl[j16][0], bl[j16][1], bl[j16][2], bl[j16][3]);
                }
#pragma unroll
                for (int i = 0; i < 2; i++)
#pragma unroll
                    for (int j = 0; j < 8; j++)
                        mma16816(acc[i][j], ah[i], &bl[j >> 1][(j & 1) * 2]);
            }
        }
    }

    const int g  = lane >> 2;
    const int tg = (lane & 3) * 2;

#pragma unroll
    for (int i = 0; i < 2; i++) {
#pragma unroll
        for (int half = 0; half < 2; half++) {
            ll m = mBase + wm + i * 16 + g + half * 8;
            ll roff = (m & 31);
            ll coff = (m >> 5);
            const float* addp = Add ?
                Add + roff * adSB + coff * adSC + nBase : (const float*)0;
            float* ofp = OutF ?
                OutF + roff * ofSB + coff * ofSC + nBase : (float*)0;
            u16* obh = OBhi ? OBhi + roff * obSB + coff * obSC + nBase : (u16*)0;
            u16* obl = OBlo ? OBlo + roff * obSB + coff * obSC + nBase : (u16*)0;
#pragma unroll
            for (int j = 0; j < 8; j++) {
                int n = wn + j * 8 + tg;
                float v0 = acc[i][j][half * 2 + 0];
                float v1 = acc[i][j][half * 2 + 1];
                if (addp) {
                    float2 a = *(const float2*)(addp + n);
                    v0 += a.x; v1 += a.y;
                }
                if (ofp)
                    *(float2*)(ofp + n) = make_float2(v0, v1);
                if (obh) {
                    u16 h0, h1, l0, l1;
                    bsplit(v0, h0, l0);
                    bsplit(v1, h1, l1);
                    *(ushort2*)(obh + n) = make_ushort2(h0, h1);
                    *(ushort2*)(obl + n) = make_ushort2(l0, l1);
                }
            }
        }
    }
}

// ---------------------------------------------------------------------------
// phase2: serial carry chain G[c+1] = G[c] @ W + u[c]; emits bf16 split of
// each produced state into GC at stride gcStep.
// ---------------------------------------------------------------------------
__device__ __forceinline__ void ffma2(ull& d, ull a, ull b) {
    asm volatile("fma.rn.f32x2 %0, %1, %2, %0;" : "+l"(d) : "l"(a), "l"(b));
}
__device__ __forceinline__ float2 u2f2(ull v) {
    float2 f;
    f.x = __uint_as_float((unsigned)(v & 0xffffffffull));
    f.y = __uint_as_float((unsigned)(v >> 32));
    return f;
}
__device__ __forceinline__ float4 ldcg4(const float* p) {
    float4 v;
    asm volatile("ld.global.cg.v4.f32 {%0,%1,%2,%3}, [%4];"
                 : "=f"(v.x), "=f"(v.y), "=f"(v.z), "=f"(v.w) : "l"(p));
    return v;
}
#define P2_RPAD 1028
#define P2_HPAD 1032
#define P2_HS_OFF (32 * P2_RPAD)
#define P2_SMEM_FLOATS (32 * P2_RPAD + 8 * P2_HPAD)
#define P2_CTAS 128

__global__ void __launch_bounds__(256) phase2_kernel(
    const float* __restrict__ ST,
    const float* __restrict__ u, ll uSB, ll uSC,
    float* __restrict__ g, ll gStep,
    u16* __restrict__ GCh, u16* __restrict__ GCl, ll gcStep,
    int steps)
{
    extern __shared__ float sm[];
    const int tid = threadIdx.x;
    const int col0 = (blockIdx.x & 31) * 32;
    const int b0   = (blockIdx.x >> 5) * 8;

    for (int idx = tid; idx < 32 * 1024; idx += 256) {
        int j = idx >> 10, k = idx & 1023;
        sm[j * P2_RPAD + k] = ST[(size_t)(col0 + j) * 1024 + k];
    }
    __syncthreads();

    const int j = tid & 31;
    const int b = tid >> 5;
    const float* Rrow = &sm[j * P2_RPAD];
    const float* hrow = &sm[P2_HS_OFF + b * P2_HPAD];
    const unsigned P = gridDim.x;

    for (int c = 0; c < steps; c++) {
        const float* gsrc = g + (ll)c * gStep;
        for (int i = tid; i < 2048; i += 256) {
            int bb = i >> 8, kk = (i & 255) * 4;
            float4 v = ldcg4(gsrc + (size_t)(b0 + bb) * UDIM + kk);
            *(float4*)&sm[P2_HS_OFF + bb * P2_HPAD + kk] = v;
        }
        __syncthreads();

        ull a0 = 0, a1 = 0, a2 = 0, a3 = 0;
#pragma unroll 4
        for (int k = 0; k < 1024; k += 8) {
            ulonglong2 h01 = *(const ulonglong2*)(hrow + k);
            ulonglong2 h23 = *(const ulonglong2*)(hrow + k + 4);
            ulonglong2 r01 = *(const ulonglong2*)(Rrow + k);
            ulonglong2 r23 = *(const ulonglong2*)(Rrow + k + 4);
            ffma2(a0, h01.x, r01.x); ffma2(a1, h01.y, r01.y);
            ffma2(a2, h23.x, r23.x); ffma2(a3, h23.y, r23.y);
        }
        float2 f0 = u2f2(a0), f1 = u2f2(a1), f2 = u2f2(a2), f3 = u2f2(a3);
        float sum = ((f0.x + f0.y) + (f1.x + f1.y)) +
                    ((f2.x + f2.y) + (f3.x + f3.y));

        float uv = __ldg(u + (ll)(b0 + b) * uSB + (ll)c * uSC + col0 + j);
        float val = sum + uv;
        ll eoff = (ll)(b0 + b) * UDIM + col0 + j;
        g[(ll)(c + 1) * gStep + eoff] = val;
        {
            u16 hh, lw;
            bsplit(val, hh, lw);
            ll gco = (ll)(c + 1) * gcStep + eoff;
            GCh[gco] = hh; GCl[gco] = lw;
        }

        __threadfence();
        __syncthreads();
        if (tid == 0) {
            unsigned arrived = atomicAdd((unsigned*)&g_bar[c], 1u) + 1u;
            if (arrived < P) {
                while (g_bar[c] < P) { }
            }
            __threadfence();
        }
        __syncthreads();
    }
}

// ---------------------------------------------------------------------------
extern "C" void kernel_launch(void* const* d_in, const int* in_sizes, int n_in,
                              void* d_out, int out_size)
{
    const float* x    = (const float*)d_in[0];
    const float* h0   = (const float*)d_in[1];
    const float* cst  = (const float*)d_in[2];
    const float* kern = (const float*)d_in[3];
    const float* rker = (const float*)d_in[4];
    float* out = (float*)d_out;

    const ll TU = (ll)TDIM * UDIM;
    const ll CU = (ll)CH * UDIM;
    const ll SL = (ll)SLE;
    const ll GB = (ll)BATCH * UDIM;
    const ll NAT_B = 1024, NAT_C = 32768;

    u16 *Xhi, *Xlo, *UAhi, *UAlo, *UBhi, *UBlo, *KThi, *KTlo;
    u16 *SPhi, *SPlo, *RPhi, *RPlo, *S32hi, *S32lo, *S64hi, *S64lo;
    u16 *C1hi, *C1lo, *C2hi, *C2lo, *GChi, *GClo;
    float *W8F, *sP1, *sP2, *sP3, *sEv, *gbuf;
    cudaGetSymbolAddress((void**)&Xhi, g_Xhi);   cudaGetSymbolAddress((void**)&Xlo, g_Xlo);
    cudaGetSymbolAddress((void**)&UAhi, g_UAhi); cudaGetSymbolAddress((void**)&UAlo, g_UAlo);
    cudaGetSymbolAddress((void**)&UBhi, g_UBhi); cudaGetSymbolAddress((void**)&UBlo, g_UBlo);
    cudaGetSymbolAddress((void**)&KThi, g_KThi); cudaGetSymbolAddress((void**)&KTlo, g_KTlo);
    cudaGetSymbolAddress((void**)&SPhi, g_SPhi); cudaGetSymbolAddress((void**)&SPlo, g_SPlo);
    cudaGetSymbolAddress((void**)&RPhi, g_RPhi); cudaGetSymbolAddress((void**)&RPlo, g_RPlo);
    cudaGetSymbolAddress((void**)&S32hi, g_S32hi); cudaGetSymbolAddress((void**)&S32lo, g_S32lo);
    cudaGetSymbolAddress((void**)&S64hi, g_S64hi); cudaGetSymbolAddress((void**)&S64lo, g_S64lo);
    cudaGetSymbolAddress((void**)&C1hi, g_C1hi); cudaGetSymbolAddress((void**)&C1lo, g_C1lo);
    cudaGetSymbolAddress((void**)&C2hi, g_C2hi); cudaGetSymbolAddress((void**)&C2lo, g_C2lo);
    cudaGetSymbolAddress((void**)&GChi, g_GChi); cudaGetSymbolAddress((void**)&GClo, g_GClo);
    cudaGetSymbolAddress((void**)&W8F, g_W8F);
    cudaGetSymbolAddress((void**)&sP1, g_sP1);
    cudaGetSymbolAddress((void**)&sP2, g_sP2);
    cudaGetSymbolAddress((void**)&sP3, g_sP3);
    cudaGetSymbolAddress((void**)&sEv, g_sEv);
    cudaGetSymbolAddress((void**)&gbuf, g_gbuf);

    cudaFuncSetAttribute(tgemm_kernel,
        cudaFuncAttributeMaxDynamicSharedMemorySize, TG_SMEM);
    cudaFuncSetAttribute(phase2_kernel,
        cudaFuncAttributeMaxDynamicSharedMemorySize, P2_SMEM_FLOATS * 4);

    // ---- streams + events (created once; capture-safe fork/join) ----
    static cudaStream_t s2 = 0, s3 = 0;
    static cudaEvent_t evFork = 0, evKT = 0, evS1 = 0, evPow = 0;
    static cudaEvent_t evChain = 0, evB3 = 0, evB2 = 0, evB1 = 0, evP3 = 0;
    static cudaEvent_t evXs[CH], evP0[CH];
    static bool tried = false;
    if (!tried) {
        tried = true;
        if (cudaStreamCreateWithFlags(&s2, cudaStreamNonBlocking) != cudaSuccess)
            s2 = 0;
        if (cudaStreamCreateWithFlags(&s3, cudaStreamNonBlocking) != cudaSuccess)
            s3 = 0;
        cudaEventCreateWithFlags(&evFork, cudaEventDisableTiming);
        cudaEventCreateWithFlags(&evKT,   cudaEventDisableTiming);
        cudaEventCreateWithFlags(&evS1,   cudaEventDisableTiming);
        cudaEventCreateWithFlags(&evPow,  cudaEventDisableTiming);
        cudaEventCreateWithFlags(&evChain, cudaEventDisableTiming);
        cudaEventCreateWithFlags(&evB3,   cudaEventDisableTiming);
        cudaEventCreateWithFlags(&evB2,   cudaEventDisableTiming);
        cudaEventCreateWithFlags(&evB1,   cudaEventDisableTiming);
        cudaEventCreateWithFlags(&evP3,   cudaEventDisableTiming);
        for (int i = 0; i < CH; i++) {
            cudaEventCreateWithFlags(&evXs[i], cudaEventDisableTiming);
            cudaEventCreateWithFlags(&evP0[i], cudaEventDisableTiming);
        }
    }

    cudaEventRecord(evFork, 0);
    cudaStreamWaitEvent(s2, evFork, 0);
    cudaStreamWaitEvent(s3, evFork, 0);

    // ======== s3: R-derived prep + full power chain ========
    bar_reset_kernel<<<(MAX_BAR + 255) / 256, 256, 0, s3>>>();
    transpose_split_kernel<<<dim3(32, 32), 256, 0, s3>>>(rker, SPhi, SPlo);    // S^1
    cudaEventRecord(evS1, s3);
    split_gather_kernel<<<UDIM, 256, 0, s3>>>(rker, NAT_B, NAT_C,
        RPhi, RPlo, NAT_B, NAT_C);                                             // R^1
    copy_h0_kernel<<<(BATCH * UDIM + 255) / 256, 256, 0, s3>>>(h0, gbuf, GChi, GClo);
    {
        dim3 g1(8, 8), g2(8, 16), g4(8, 32), g8(8, 64);
        tgemm_kernel<<<g1, 256, TG_SMEM, s3>>>(SPhi, SPlo, NAT_B, NAT_C, RPhi, RPlo,
            nullptr, 0, 0, nullptr, 0, 0, SPhi + SL, SPlo + SL, NAT_B, NAT_C);      // S^2
        tgemm_kernel<<<g1, 256, TG_SMEM, s3>>>(RPhi, RPlo, NAT_B, NAT_C, SPhi, SPlo,
            nullptr, 0, 0, nullptr, 0, 0, RPhi + SL, RPlo + SL, NAT_B, NAT_C);      // R^2
        tgemm_kernel<<<g2, 256, TG_SMEM, s3>>>(SPhi, SPlo, NAT_B, NAT_C,
            RPhi + SL, RPlo + SL,
            nullptr, 0, 0, nullptr, 0, 0, SPhi + 2 * SL, SPlo + 2 * SL, NAT_B, NAT_C); // S^3,4
        tgemm_kernel<<<g1, 256, TG_SMEM, s3>>>(RPhi + SL, RPlo + SL, NAT_B, NAT_C,
            SPhi + SL, SPlo + SL,
            nullptr, 0, 0, nullptr, 0, 0, RPhi + 2 * SL, RPlo + 2 * SL, NAT_B, NAT_C); // R^4
        tgemm_kernel<<<g4, 256, TG_SMEM, s3>>>(SPhi, SPlo, NAT_B, NAT_C,
            RPhi + 2 * SL, RPlo + 2 * SL,
            nullptr, 0, 0, nullptr, 0, 0, SPhi + 4 * SL, SPlo + 4 * SL, NAT_B, NAT_C); // S^5..8
        tgemm_kernel<<<g1, 256, TG_SMEM, s3>>>(RPhi + 2 * SL, RPlo + 2 * SL, NAT_B, NAT_C,
            SPhi + 3 * SL, SPlo + 3 * SL,
            nullptr, 0, 0, nullptr, 0, 0, RPhi + 3 * SL, RPlo + 3 * SL, NAT_B, NAT_C); // R^8
        tgemm_kernel<<<g8, 256, TG_SMEM, s3>>>(SPhi, SPlo, NAT_B, NAT_C,
            RPhi + 3 * SL, RPlo + 3 * SL,
            nullptr, 0, 0, nullptr, 0, 0, SPhi + 8 * SL, SPlo + 8 * SL, NAT_B, NAT_C); // S^9..16
        tgemm_kernel<<<g1, 256, TG_SMEM, s3>>>(RPhi + 3 * SL, RPlo + 3 * SL, NAT_B, NAT_C,
            SPhi + 7 * SL, SPlo + 7 * SL,
            nullptr, 0, 0, nullptr, 0, 0, RPhi + 4 * SL, RPlo + 4 * SL, NAT_B, NAT_C); // R^16
        tgemm_kernel<<<g1, 256, TG_SMEM, s3>>>(RPhi + 4 * SL, RPlo + 4 * SL, NAT_B, NAT_C,
            SPhi + 15 * SL, SPlo + 15 * SL,
            nullptr, 0, 0, nullptr, 0, 0, RPhi + 5 * SL, RPlo + 5 * SL, NAT_B, NAT_C); // R^32
        tgemm_kernel<<<g1, 256, TG_SMEM, s3>>>(SPhi + 15 * SL, SPlo + 15 * SL, NAT_B, NAT_C,
            RPhi + 4 * SL, RPlo + 4 * SL,
            nullptr, 0, 0, nullptr, 0, 0, S32hi, S32lo, NAT_B, NAT_C);               // S^32
        tgemm_kernel<<<g1, 256, TG_SMEM, s3>>>(RPhi + 5 * SL, RPlo + 5 * SL, NAT_B, NAT_C,
            S32hi, S32lo,
            nullptr, 0, 0, nullptr, 0, 0, RPhi + 6 * SL, RPlo + 6 * SL, NAT_B, NAT_C); // R^64
        tgemm_kernel<<<g1, 256, TG_SMEM, s3>>>(S32hi, S32lo, NAT_B, NAT_C,
            RPhi + 5 * SL, RPlo + 5 * SL,
            nullptr, 0, 0, nullptr, 0, 0, S64hi, S64lo, NAT_B, NAT_C);               // S^64
        tgemm_kernel<<<g1, 256, TG_SMEM, s3>>>(S64hi, S64lo, NAT_B, NAT_C,
            RPhi + 6 * SL, RPlo + 6 * SL,
            nullptr, 0, 0, W8F, NAT_B, NAT_C, nullptr, nullptr, 0, 0);               // S^128 fp32
    }
    cudaEventRecord(evPow, s3);

    // ======== main: K^T, then x split sliced by t mod 16 ========
    transpose_split_kernel<<<dim3(32, 32), 256>>>(kern, KThi, KTlo);
    cudaEventRecord(evKT, 0);
    cudaStreamWaitEvent(s2, evKT, 0);
    for (int j = 0; j < CH; j++) {
        split_gather_kernel<<<NCH * BATCH, 256>>>(x + (ll)j * 1024, TU, (ll)16 * 1024,
            Xhi + (ll)j * 1024, Xlo + (ll)j * 1024, TU, (ll)16 * 1024);
        cudaEventRecord(evXs[j], 0);
        cudaStreamWaitEvent(s2, evXs[j], 0);
        dim3 gp(8, 32);
        tgemm_kernel<<<gp, 256, TG_SMEM, s2>>>(
            Xhi + (ll)j * 1024, Xlo + (ll)j * 1024, TU, (ll)16 * 1024,
            KThi, KTlo,
            cst, 1024, 0,
            out + (ll)j * 1024, TU, CU,
            (j == 0) ? UAhi : nullptr, (j == 0) ? UAlo : nullptr, NAT_B, NAT_C);
        cudaEventRecord(evP0[j], s2);
    }

    // ======== main: phase 1 Horner chain ========
    cudaStreamWaitEvent(0, evS1, 0);
    cudaStreamWaitEvent(0, evP0[0], 0);
    {
        dim3 gp(8, 32);   // M = 4096
        for (int jj = 1; jj < CH; jj++) {
            const u16* ah = (jj & 1) ? UAhi : UBhi;
            const u16* al = (jj & 1) ? UAlo : UBlo;
            u16* oh = (jj & 1) ? UBhi : UAhi;
            u16* ol = (jj & 1) ? UBlo : UAlo;
            cudaStreamWaitEvent(0, evP0[jj], 0);
            tgemm_kernel<<<gp, 256, TG_SMEM>>>(ah, al, NAT_B, NAT_C,
                SPhi, SPlo,
                out + (ll)jj * 1024, TU, CU,
                out + (ll)jj * 1024, TU, CU,
                oh, ol, NAT_B, NAT_C);
        }
    }

    cudaStreamWaitEvent(0, evPow, 0);

    // ---- radix-8 carry reduction: W = R^16 ----
    const float* sBase = out + (ll)(CH - 1) * 1024;

    // Snapshot even-chunk s_{2d} fp32 (race fix vs phase-3 residue writes).
    copy_rows_kernel<<<2048, 256>>>(sBase, TU, 2 * CU, sEv, NAT_B, NAT_C);

    tgemm_kernel<<<dim3(8, 16), 256, TG_SMEM>>>(UBhi, UBlo, NAT_B, 2 * NAT_C,
        SPhi + 15 * SL, SPlo + 15 * SL,
        sBase + CU, TU, 2 * CU,
        sP1, NAT_B, NAT_C,
        C1hi, C1lo, NAT_B, NAT_C);                                   // combine1
    tgemm_kernel<<<dim3(8, 8), 256, TG_SMEM>>>(C1hi, C1lo, NAT_B, 2 * NAT_C,
        S32hi, S32lo,
        sP1 + NAT_C, NAT_B, 2 * NAT_C,
        sP2, NAT_B, NAT_C,
        C2hi, C2lo, NAT_B, NAT_C);                                   // combine2
    tgemm_kernel<<<dim3(8, 4), 256, TG_SMEM>>>(C2hi, C2lo, NAT_B, 2 * NAT_C,
        S64hi, S64lo,
        sP2 + NAT_C, NAT_B, 2 * NAT_C,
        sP3, NAT_B, NAT_C,
        nullptr, nullptr, 0, 0);                                     // combine3

    phase2_kernel<<<P2_CTAS, 256, P2_SMEM_FLOATS * 4>>>(
        W8F, sP3, NAT_B, NAT_C, gbuf, 8 * GB, GChi, GClo, 8 * NAT_C, 15);
    cudaEventRecord(evChain, 0);

    // s2: phase3 residue c ≡ 0 (mod 8)
    cudaStreamWaitEvent(s2, evChain, 0);
    tgemm_kernel<<<dim3(128, 4), 256, TG_SMEM, s2>>>(GChi, GClo, NAT_B, 8 * NAT_C,
        SPhi, SPlo,
        out, TU, 8 * CU,
        out, TU, 8 * CU,
        nullptr, nullptr, 0, 0);

    tgemm_kernel<<<dim3(8, 4), 256, TG_SMEM>>>(GChi, GClo, NAT_B, 8 * NAT_C,
        S64hi, S64lo,
        sP2, NAT_B, 2 * NAT_C,
        nullptr, 0, 0,
        GChi + 4 * NAT_C, GClo + 4 * NAT_C, NAT_B, 8 * NAT_C);       // backfill3
    cudaEventRecord(evB3, 0);

    // s2: phase3 residue c ≡ 4 (mod 8)
    cudaStreamWaitEvent(s2, evB3, 0);
    tgemm_kernel<<<dim3(128, 4), 256, TG_SMEM, s2>>>(
        GChi + 4 * NAT_C, GClo + 4 * NAT_C, NAT_B, 8 * NAT_C,
        SPhi, SPlo,
        out + 4 * CU, TU, 8 * CU,
        out + 4 * CU, TU, 8 * CU,
        nullptr, nullptr, 0, 0);

    tgemm_kernel<<<dim3(8, 8), 256, TG_SMEM>>>(GChi, GClo, NAT_B, 4 * NAT_C,
        S32hi, S32lo,
        sP1, NAT_B, 2 * NAT_C,
        nullptr, 0, 0,
        GChi + 2 * NAT_C, GClo + 2 * NAT_C, NAT_B, 4 * NAT_C);       // backfill2
    cudaEventRecord(evB2, 0);

    // s2: phase3 residue c ≡ 2 (mod 4)
    cudaStreamWaitEvent(s2, evB2, 0);
    tgemm_kernel<<<dim3(128, 8), 256, TG_SMEM, s2>>>(
        GChi + 2 * NAT_C, GClo + 2 * NAT_C, NAT_B, 4 * NAT_C,
        SPhi, SPlo,
        out + 2 * CU, TU, 4 * CU,
        out + 2 * CU, TU, 4 * CU,
        nullptr, nullptr, 0, 0);

    // backfill1 reads the SNAPSHOT of even s (race-free)
    tgemm_kernel<<<dim3(8, 16), 256, TG_SMEM>>>(GChi, GClo, NAT_B, 2 * NAT_C,
        SPhi + 15 * SL, SPlo + 15 * SL,
        sEv, NAT_B, NAT_C,
        nullptr, 0, 0,
        GChi + NAT_C, GClo + NAT_C, NAT_B, 2 * NAT_C);               // backfill1
    cudaEventRecord(evB1, 0);

    // s2: phase3 odd residues
    cudaStreamWaitEvent(s2, evB1, 0);
    tgemm_kernel<<<dim3(128, 16), 256, TG_SMEM, s2>>>(
        GChi + NAT_C, GClo + NAT_C, NAT_B, 2 * NAT_C,
        SPhi, SPlo,
        out + CU, TU, 2 * CU,
        out + CU, TU, 2 * CU,
        nullptr, nullptr, 0, 0);

    // join s2 back into the capture stream
    cudaEventRecord(evP3, s2);
    cudaStreamWaitEvent(0, evP3, 0);
}

// round 16
// speedup vs baseline: 1.0564x; 1.0035x over previous
#include <cuda_runtime.h>
#include <cuda_bf16.h>
#include <cstdint>

typedef unsigned long long ull;
typedef long long ll;
typedef unsigned short u16;
typedef unsigned int u32;

#define UDIM 1024
#define BATCH 32
#define TDIM 2048
#define CH 16
#define NCH (TDIM / CH)          // 128
#define SLE (1024 * 1024)

// ---------------- scratch (device globals; no runtime alloc) ----------------
__device__ u16   g_Xhi[(size_t)BATCH * TDIM * UDIM];
__device__ u16   g_Xlo[(size_t)BATCH * TDIM * UDIM];
__device__ u16   g_UAhi[NCH * BATCH * UDIM], g_UAlo[NCH * BATCH * UDIM];
__device__ u16   g_UBhi[NCH * BATCH * UDIM], g_UBlo[NCH * BATCH * UDIM];
__device__ u16   g_KThi[SLE], g_KTlo[SLE];
__device__ u16   g_SPhi[CH * SLE], g_SPlo[CH * SLE];    // S^1..S^16
__device__ u16   g_S32hi[SLE], g_S32lo[SLE];            // S^32
__device__ u16   g_S64hi[SLE], g_S64lo[SLE];            // S^64
__device__ u16   g_RPhi[7 * SLE], g_RPlo[7 * SLE];      // R^1,2,4,8,16,32,64
__device__ u16   g_C1hi[64 * BATCH * UDIM], g_C1lo[64 * BATCH * UDIM];
__device__ u16   g_C2hi[32 * BATCH * UDIM], g_C2lo[32 * BATCH * UDIM];
__device__ u16   g_GChi[NCH * BATCH * UDIM], g_GClo[NCH * BATCH * UDIM];
__device__ float g_W8F[SLE];                // S^128 fp32 (serial chain weight)
__device__ float g_sP1[64 * BATCH * UDIM];
__device__ float g_sP2[32 * BATCH * UDIM];
__device__ float g_sP3[16 * BATCH * UDIM];
__device__ float g_sEv[64 * BATCH * UDIM];  // snapshot of even-chunk s_{2d}
__device__ float g_gbuf[NCH * BATCH * UDIM];

#define MAX_BAR 2048
__device__ volatile unsigned g_bar[MAX_BAR];

__global__ void __launch_bounds__(256) bar_reset_kernel() {
    int i = blockIdx.x * blockDim.x + threadIdx.x;
    if (i < MAX_BAR) *(unsigned*)&g_bar[i] = 0u;
}

// ---------------- helpers ----------------
__device__ __forceinline__ u32 smem_u32(const void* p) {
    u32 a;
    asm("{ .reg .u64 t; cvta.to.shared.u64 t, %1; cvt.u32.u64 %0, t; }"
        : "=r"(a) : "l"(p));
    return a;
}
#define SWZ64(o) ((o) ^ (((o) >> 3) & 0x30))

__device__ __forceinline__ void bsplit(float v, u16& h, u16& l) {
    __nv_bfloat16 bh = __float2bfloat16_rn(v);
    float r = v - __bfloat162float(bh);
    __nv_bfloat16 bl = __float2bfloat16_rn(r);
    h = __bfloat16_as_ushort(bh);
    l = __bfloat16_as_ushort(bl);
}

__global__ void __launch_bounds__(256) copy_h0_kernel(
    const float* __restrict__ h0, float* __restrict__ g,
    u16* __restrict__ GCh, u16* __restrict__ GCl)
{
    int i = blockIdx.x * blockDim.x + threadIdx.x;
    if (i < BATCH * UDIM) {
        float v = h0[i];
        g[i] = v;
        u16 h, l;
        bsplit(v, h, l);
        GCh[i] = h; GCl[i] = l;
    }
}

// fp32 strided-row copy (row m -> (m&31)*sB + (m>>5)*sC, dst likewise)
__global__ void __launch_bounds__(256) copy_rows_kernel(
    const float* __restrict__ src, ll sB, ll sC,
    float* __restrict__ dst, ll dB, ll dC)
{
    int m = blockIdx.x;
    int k = threadIdx.x * 4;
    ll soff = (ll)(m & 31) * sB + (ll)(m >> 5) * sC + k;
    ll doff = (ll)(m & 31) * dB + (ll)(m >> 5) * dC + k;
    *(float4*)(dst + doff) = *(const float4*)(src + soff);
}

__device__ __forceinline__ void ldsm4(u32 addr, u32& r0, u32& r1, u32& r2, u32& r3) {
    asm volatile("ldmatrix.sync.aligned.m8n8.x4.shared.b16 {%0,%1,%2,%3}, [%4];"
                 : "=r"(r0), "=r"(r1), "=r"(r2), "=r"(r3) : "r"(addr));
}
__device__ __forceinline__ void mma16816(float* d, const u32* a, const u32* b) {
    asm volatile(
        "mma.sync.aligned.m16n8k16.row.col.f32.bf16.bf16.f32 "
        "{%0,%1,%2,%3}, {%4,%5,%6,%7}, {%8,%9}, {%0,%1,%2,%3};"
        : "+f"(d[0]), "+f"(d[1]), "+f"(d[2]), "+f"(d[3])
        : "r"(a[0]), "r"(a[1]), "r"(a[2]), "r"(a[3]), "r"(b[0]), "r"(b[1]));
}

// ------ split_gather: fp32 strided rows -> bf16 hi/lo at strided out -------
__global__ void __launch_bounds__(256) split_gather_kernel(
    const float* __restrict__ src, ll sB, ll sC,
    u16* __restrict__ hi, u16* __restrict__ lo, ll dB, ll dC)
{
    int m = blockIdx.x;
    int k = threadIdx.x * 4;
    ll off = (ll)(m & 31) * sB + (ll)(m >> 5) * sC + k;
    float4 v = *(const float4*)(src + off);
    u16 h0, h1, h2, h3, l0, l1, l2, l3;
    bsplit(v.x, h0, l0); bsplit(v.y, h1, l1);
    bsplit(v.z, h2, l2); bsplit(v.w, h3, l3);
    ll doff = (ll)(m & 31) * dB + (ll)(m >> 5) * dC + k;
    *(ushort4*)(hi + doff) = make_ushort4(h0, h1, h2, h3);
    *(ushort4*)(lo + doff) = make_ushort4(l0, l1, l2, l3);
}

// ------------- transpose_split: fp32 W[k][n] -> bf16 hi/lo of W^T [n][k] ----
__global__ void __launch_bounds__(256) transpose_split_kernel(
    const float* __restrict__ src, u16* __restrict__ thi, u16* __restrict__ tlo)
{
    __shared__ float tile[32][33];
    int bx = blockIdx.x * 32;
    int by = blockIdx.y * 32;
    int tx = threadIdx.x & 31;
    int ty = threadIdx.x >> 5;
#pragma unroll
    for (int i = 0; i < 32; i += 8)
        tile[ty + i][tx] = src[(ll)(by + ty + i) * 1024 + bx + tx];
    __syncthreads();
#pragma unroll
    for (int i = 0; i < 32; i += 8) {
        u16 h, l;
        bsplit(tile[tx][ty + i], h, l);
        ll off = (ll)(bx + ty + i) * 1024 + (by + tx);
        thi[off] = h;
        tlo[off] = l;
    }
}

// ---------------------------------------------------------------------------
// tgemm (round-14 engine, operand-shared BK=32, 2 CTAs/SM):
//   C[m][n] = sum_k Af[m][k]*Bf[n][k] via bf16 split. Each stage holds
//   Ahi/Alo/Bhi/Blo 128x32 tiles (4 x 8KB, SW64); per k16 the 3 products
//   (hi*hi, lo*hi, hi*lo) reuse resident tiles. 3 stages = 96KB.
// Row maps: (m&31)*SB + (m>>5)*SC for A/Add/OutF/OB. B natural [n][k].
// ---------------------------------------------------------------------------
#define TG_STAGE 32768
#define TG_SMEM (3 * TG_STAGE)
#define TG_NCHK 32

__global__ void __launch_bounds__(256, 2) tgemm_kernel(
    const u16* __restrict__ Ahi, const u16* __restrict__ Alo, ll aSB, ll aSC,
    const u16* __restrict__ Bhi, const u16* __restrict__ Blo,
    const float* __restrict__ Add, ll adSB, ll adSC,
    float* __restrict__ OutF, ll ofSB, ll ofSC,
    u16* __restrict__ OBhi, u16* __restrict__ OBlo, ll obSB, ll obSC)
{
    extern __shared__ char smraw[];
    const u32 smbase = smem_u32(smraw);

    const int tid  = threadIdx.x;
    const int wid  = tid >> 5;
    const int lane = tid & 31;
    const ll mBase = (ll)blockIdx.y * 128;
    const ll nBase = (ll)blockIdx.x * 128;

    const int wm = (wid >> 1) * 32;
    const int wn = (wid & 1) * 64;

    float acc[2][8][4];
#pragma unroll
    for (int i = 0; i < 2; i++)
#pragma unroll
        for (int j = 0; j < 8; j++)
#pragma unroll
            for (int q = 0; q < 4; q++) acc[i][j][q] = 0.0f;

    auto load_chunk = [&](int c, int s) {
        const ll kbase = (ll)c * 32;
        u32 base = smbase + (u32)s * TG_STAGE;
#pragma unroll
        for (int i = 0; i < 2; i++) {
            int idx = i * 256 + tid;
            int row = idx >> 2;
            int q   = (idx & 3) * 16;
            u32 sw  = SWZ64((u32)(row * 64 + q));
            ll  kel = kbase + (idx & 3) * 8;
            ll  rm  = mBase + row;
            ll aoff = (rm & 31) * aSB + (rm >> 5) * aSC + kel;
            ll boff = (nBase + row) * 1024 + kel;
            asm volatile("cp.async.cg.shared.global [%0], [%1], 16;"
                :: "r"(base + sw), "l"((ull)(uintptr_t)(Ahi + aoff)));
            asm volatile("cp.async.cg.shared.global [%0], [%1], 16;"
                :: "r"(base + 8192 + sw), "l"((ull)(uintptr_t)(Alo + aoff)));
            asm volatile("cp.async.cg.shared.global [%0], [%1], 16;"
                :: "r"(base + 16384 + sw), "l"((ull)(uintptr_t)(Bhi + boff)));
            asm volatile("cp.async.cg.shared.global [%0], [%1], 16;"
                :: "r"(base + 24576 + sw), "l"((ull)(uintptr_t)(Blo + boff)));
        }
        asm volatile("cp.async.commit_group;" ::: "memory");
    };

    load_chunk(0, 0);
    load_chunk(1, 1);

    const int aRow = (lane & 15);
    const int aKb  = (lane >> 4) * 16;
    const int bRow = (lane & 7) + ((lane >> 4) << 3);
    const int bKb  = ((lane >> 3) & 1) * 16;

#pragma unroll 1
    for (int c = 0; c < TG_NCHK; c++) {
        if (c + 2 < TG_NCHK) {
            asm volatile("cp.async.wait_group 1;" ::: "memory");
        } else {
            asm volatile("cp.async.wait_group 0;" ::: "memory");
        }
        __syncthreads();
        if (c + 2 < TG_NCHK) load_chunk(c + 2, (c + 2) % 3);

        u32 base = smbase + (u32)(c % 3) * TG_STAGE;

#pragma unroll
        for (int k16 = 0; k16 < 2; k16++) {
            const int kb = k16 * 32;
            // hi*hi
            u32 ah[2][4];
#pragma unroll
            for (int i = 0; i < 2; i++) {
                u32 ad = base + SWZ64((u32)((wm + i * 16 + aRow) * 64 + kb + aKb));
                ldsm4(ad, ah[i][0], ah[i][1], ah[i][2], ah[i][3]);
            }
            u32 bh[4][4];
#pragma unroll
            for (int j16 = 0; j16 < 4; j16++) {
                u32 bd = base + 16384 +
                         SWZ64((u32)((wn + j16 * 16 + bRow) * 64 + kb + bKb));
                ldsm4(bd, bh[j16][0], bh[j16][1], bh[j16][2], bh[j16][3]);
            }
#pragma unroll
            for (int i = 0; i < 2; i++)
#pragma unroll
                for (int j = 0; j < 8; j++)
                    mma16816(acc[i][j], ah[i], &bh[j >> 1][(j & 1) * 2]);

            // lo*hi (al transient; bh reused then dead)
            {
                u32 al[2][4];
#pragma unroll
                for (int i = 0; i < 2; i++) {
                    u32 ad = base + 8192 +
                             SWZ64((u32)((wm + i * 16 + aRow) * 64 + kb + aKb));
                    ldsm4(ad, al[i][0], al[i][1], al[i][2], al[i][3]);
                }
#pragma unroll
                for (int i = 0; i < 2; i++)
#pragma unroll
                    for (int j = 0; j < 8; j++)
                        mma16816(acc[i][j], al[i], &bh[j >> 1][(j & 1) * 2]);
            }

            // hi*lo (bl loaded after bh dead; ah reused)
            {
                u32 bl[4][4];
#pragma unroll
                for (int j16 = 0; j16 < 4; j16++) {
                    u32 bd = base + 24576 +
                             SWZ64((u32)((wn + j16 * 16 + bRow) * 64 + kb + bKb));
                    ldsm4(bd, bl[j16][0], bl[j16][1], bl[j16][2], bl[j16][3]);
                }
#pragma unroll
                for (int i = 0; i < 2; i++)
#pragma unroll
                    for (int j = 0; j < 8; j++)
                        mma16816(acc[i][j], ah[i], &bl[j >> 1][(j & 1) * 2]);
            }
        }
    }

    const int g  = lane >> 2;
    const int tg = (lane & 3) * 2;

#pragma unroll
    for (int i = 0; i < 2; i++) {
#pragma unroll
        for (int half = 0; half < 2; half++) {
            ll m = mBase + wm + i * 16 + g + half * 8;
            ll roff = (m & 31);
            ll coff = (m >> 5);
            const float* addp = Add ?
                Add + roff * adSB + coff * adSC + nBase : (const float*)0;
            float* ofp = OutF ?
                OutF + roff * ofSB + coff * ofSC + nBase : (float*)0;
            u16* obh = OBhi ? OBhi + roff * obSB + coff * obSC + nBase : (u16*)0;
            u16* obl = OBlo ? OBlo + roff * obSB + coff * obSC + nBase : (u16*)0;
#pragma unroll
            for (int j = 0; j < 8; j++) {
                int n = wn + j * 8 + tg;
                float v0 = acc[i][j][half * 2 + 0];
                float v1 = acc[i][j][half * 2 + 1];
                if (addp) {
                    float2 a = *(const float2*)(addp + n);
                    v0 += a.x; v1 += a.y;
                }
                if (ofp)
                    *(float2*)(ofp + n) = make_float2(v0, v1);
                if (obh) {
                    u16 h0, h1, l0, l1;
                    bsplit(v0, h0, l0);
                    bsplit(v1, h1, l1);
                    *(ushort2*)(obh + n) = make_ushort2(h0, h1);
                    *(ushort2*)(obl + n) = make_ushort2(l0, l1);
                }
            }
        }
    }
}

// ---------------------------------------------------------------------------
// phase2: serial carry chain G[c+1] = G[c] @ W + u[c]; emits bf16 split of
// each produced state into GC at stride gcStep.
// ---------------------------------------------------------------------------
__device__ __forceinline__ void ffma2(ull& d, ull a, ull b) {
    asm volatile("fma.rn.f32x2 %0, %1, %2, %0;" : "+l"(d) : "l"(a), "l"(b));
}
__device__ __forceinline__ float2 u2f2(ull v) {
    float2 f;
    f.x = __uint_as_float((unsigned)(v & 0xffffffffull));
    f.y = __uint_as_float((unsigned)(v >> 32));
    return f;
}
__device__ __forceinline__ float4 ldcg4(const float* p) {
    float4 v;
    asm volatile("ld.global.cg.v4.f32 {%0,%1,%2,%3}, [%4];"
                 : "=f"(v.x), "=f"(v.y), "=f"(v.z), "=f"(v.w) : "l"(p));
    return v;
}
#define P2_RPAD 1028
#define P2_HPAD 1032
#define P2_HS_OFF (32 * P2_RPAD)
#define P2_SMEM_FLOATS (32 * P2_RPAD + 8 * P2_HPAD)
#define P2_CTAS 128

__global__ void __launch_bounds__(256) phase2_kernel(
    const float* __restrict__ ST,
    const float* __restrict__ u, ll uSB, ll uSC,
    float* __restrict__ g, ll gStep,
    u16* __restrict__ GCh, u16* __restrict__ GCl, ll gcStep,
    int steps)
{
    extern __shared__ float sm[];
    const int tid = threadIdx.x;
    const int col0 = (blockIdx.x & 31) * 32;
    const int b0   = (blockIdx.x >> 5) * 8;

    for (int idx = tid; idx < 32 * 1024; idx += 256) {
        int j = idx >> 10, k = idx & 1023;
        sm[j * P2_RPAD + k] = ST[(size_t)(col0 + j) * 1024 + k];
    }
    __syncthreads();

    const int j = tid & 31;
    const int b = tid >> 5;
    const float* Rrow = &sm[j * P2_RPAD];
    const float* hrow = &sm[P2_HS_OFF + b * P2_HPAD];
    const unsigned P = gridDim.x;

    for (int c = 0; c < steps; c++) {
        const float* gsrc = g + (ll)c * gStep;
        for (int i = tid; i < 2048; i += 256) {
            int bb = i >> 8, kk = (i & 255) * 4;
            float4 v = ldcg4(gsrc + (size_t)(b0 + bb) * UDIM + kk);
            *(float4*)&sm[P2_HS_OFF + bb * P2_HPAD + kk] = v;
        }
        __syncthreads();

        ull a0 = 0, a1 = 0, a2 = 0, a3 = 0;
#pragma unroll 4
        for (int k = 0; k < 1024; k += 8) {
            ulonglong2 h01 = *(const ulonglong2*)(hrow + k);
            ulonglong2 h23 = *(const ulonglong2*)(hrow + k + 4);
            ulonglong2 r01 = *(const ulonglong2*)(Rrow + k);
            ulonglong2 r23 = *(const ulonglong2*)(Rrow + k + 4);
            ffma2(a0, h01.x, r01.x); ffma2(a1, h01.y, r01.y);
            ffma2(a2, h23.x, r23.x); ffma2(a3, h23.y, r23.y);
        }
        float2 f0 = u2f2(a0), f1 = u2f2(a1), f2 = u2f2(a2), f3 = u2f2(a3);
        float sum = ((f0.x + f0.y) + (f1.x + f1.y)) +
                    ((f2.x + f2.y) + (f3.x + f3.y));

        float uv = __ldg(u + (ll)(b0 + b) * uSB + (ll)c * uSC + col0 + j);
        float val = sum + uv;
        ll eoff = (ll)(b0 + b) * UDIM + col0 + j;
        g[(ll)(c + 1) * gStep + eoff] = val;
        {
            u16 hh, lw;
            bsplit(val, hh, lw);
            ll gco = (ll)(c + 1) * gcStep + eoff;
            GCh[gco] = hh; GCl[gco] = lw;
        }

        __threadfence();
        __syncthreads();
        if (tid == 0) {
            unsigned arrived = atomicAdd((unsigned*)&g_bar[c], 1u) + 1u;
            if (arrived < P) {
                while (g_bar[c] < P) { }
            }
            __threadfence();
        }
        __syncthreads();
    }
}

// ---------------------------------------------------------------------------
extern "C" void kernel_launch(void* const* d_in, const int* in_sizes, int n_in,
                              void* d_out, int out_size)
{
    const float* x    = (const float*)d_in[0];
    const float* h0   = (const float*)d_in[1];
    const float* cst  = (const float*)d_in[2];
    const float* kern = (const float*)d_in[3];
    const float* rker = (const float*)d_in[4];
    float* out = (float*)d_out;

    const ll TU = (ll)TDIM * UDIM;
    const ll CU = (ll)CH * UDIM;
    const ll SL = (ll)SLE;
    const ll GB = (ll)BATCH * UDIM;
    const ll NAT_B = 1024, NAT_C = 32768;

    u16 *Xhi, *Xlo, *UAhi, *UAlo, *UBhi, *UBlo, *KThi, *KTlo;
    u16 *SPhi, *SPlo, *RPhi, *RPlo, *S32hi, *S32lo, *S64hi, *S64lo;
    u16 *C1hi, *C1lo, *C2hi, *C2lo, *GChi, *GClo;
    float *W8F, *sP1, *sP2, *sP3, *sEv, *gbuf;
    cudaGetSymbolAddress((void**)&Xhi, g_Xhi);   cudaGetSymbolAddress((void**)&Xlo, g_Xlo);
    cudaGetSymbolAddress((void**)&UAhi, g_UAhi); cudaGetSymbolAddress((void**)&UAlo, g_UAlo);
    cudaGetSymbolAddress((void**)&UBhi, g_UBhi); cudaGetSymbolAddress((void**)&UBlo, g_UBlo);
    cudaGetSymbolAddress((void**)&KThi, g_KThi); cudaGetSymbolAddress((void**)&KTlo, g_KTlo);
    cudaGetSymbolAddress((void**)&SPhi, g_SPhi); cudaGetSymbolAddress((void**)&SPlo, g_SPlo);
    cudaGetSymbolAddress((void**)&RPhi, g_RPhi); cudaGetSymbolAddress((void**)&RPlo, g_RPlo);
    cudaGetSymbolAddress((void**)&S32hi, g_S32hi); cudaGetSymbolAddress((void**)&S32lo, g_S32lo);
    cudaGetSymbolAddress((void**)&S64hi, g_S64hi); cudaGetSymbolAddress((void**)&S64lo, g_S64lo);
    cudaGetSymbolAddress((void**)&C1hi, g_C1hi); cudaGetSymbolAddress((void**)&C1lo, g_C1lo);
    cudaGetSymbolAddress((void**)&C2hi, g_C2hi); cudaGetSymbolAddress((void**)&C2lo, g_C2lo);
    cudaGetSymbolAddress((void**)&GChi, g_GChi); cudaGetSymbolAddress((void**)&GClo, g_GClo);
    cudaGetSymbolAddress((void**)&W8F, g_W8F);
    cudaGetSymbolAddress((void**)&sP1, g_sP1);
    cudaGetSymbolAddress((void**)&sP2, g_sP2);
    cudaGetSymbolAddress((void**)&sP3, g_sP3);
    cudaGetSymbolAddress((void**)&sEv, g_sEv);
    cudaGetSymbolAddress((void**)&gbuf, g_gbuf);

    cudaFuncSetAttribute(tgemm_kernel,
        cudaFuncAttributeMaxDynamicSharedMemorySize, TG_SMEM);
    cudaFuncSetAttribute(phase2_kernel,
        cudaFuncAttributeMaxDynamicSharedMemorySize, P2_SMEM_FLOATS * 4);

    // ---- streams + events (created once; capture-safe fork/join) ----
    static cudaStream_t s2 = 0, s3 = 0;
    static cudaEvent_t evFork = 0, evKT = 0, evS1 = 0, evPow = 0;
    static cudaEvent_t evChain = 0, evB3 = 0, evB2 = 0, evB1 = 0, evP3 = 0;
    static cudaEvent_t evS = 0, evSnap = 0;
    static cudaEvent_t evXs[CH], evP0[CH];
    static bool tried = false;
    if (!tried) {
        tried = true;
        if (cudaStreamCreateWithFlags(&s2, cudaStreamNonBlocking) != cudaSuccess)
            s2 = 0;
        if (cudaStreamCreateWithFlags(&s3, cudaStreamNonBlocking) != cudaSuccess)
            s3 = 0;
        cudaEventCreateWithFlags(&evFork, cudaEventDisableTiming);
        cudaEventCreateWithFlags(&evKT,   cudaEventDisableTiming);
        cudaEventCreateWithFlags(&evS1,   cudaEventDisableTiming);
        cudaEventCreateWithFlags(&evPow,  cudaEventDisableTiming);
        cudaEventCreateWithFlags(&evChain, cudaEventDisableTiming);
        cudaEventCreateWithFlags(&evB3,   cudaEventDisableTiming);
        cudaEventCreateWithFlags(&evB2,   cudaEventDisableTiming);
        cudaEventCreateWithFlags(&evB1,   cudaEventDisableTiming);
        cudaEventCreateWithFlags(&evP3,   cudaEventDisableTiming);
        cudaEventCreateWithFlags(&evS,    cudaEventDisableTiming);
        cudaEventCreateWithFlags(&evSnap, cudaEventDisableTiming);
        for (int i = 0; i < CH; i++) {
            cudaEventCreateWithFlags(&evXs[i], cudaEventDisableTiming);
            cudaEventCreateWithFlags(&evP0[i], cudaEventDisableTiming);
        }
    }

    cudaEventRecord(evFork, 0);
    cudaStreamWaitEvent(s2, evFork, 0);
    cudaStreamWaitEvent(s3, evFork, 0);

    // ======== s3: R-derived prep + full power chain ========
    bar_reset_kernel<<<(MAX_BAR + 255) / 256, 256, 0, s3>>>();
    transpose_split_kernel<<<dim3(32, 32), 256, 0, s3>>>(rker, SPhi, SPlo);    // S^1
    cudaEventRecord(evS1, s3);
    split_gather_kernel<<<UDIM, 256, 0, s3>>>(rker, NAT_B, NAT_C,
        RPhi, RPlo, NAT_B, NAT_C);                                             // R^1
    copy_h0_kernel<<<(BATCH * UDIM + 255) / 256, 256, 0, s3>>>(h0, gbuf, GChi, GClo);
    {
        dim3 g1(8, 8), g2(8, 16), g4(8, 32), g8(8, 64);
        tgemm_kernel<<<g1, 256, TG_SMEM, s3>>>(SPhi, SPlo, NAT_B, NAT_C, RPhi, RPlo,
            nullptr, 0, 0, nullptr, 0, 0, SPhi + SL, SPlo + SL, NAT_B, NAT_C);      // S^2
        tgemm_kernel<<<g1, 256, TG_SMEM, s3>>>(RPhi, RPlo, NAT_B, NAT_C, SPhi, SPlo,
            nullptr, 0, 0, nullptr, 0, 0, RPhi + SL, RPlo + SL, NAT_B, NAT_C);      // R^2
        tgemm_kernel<<<g2, 256, TG_SMEM, s3>>>(SPhi, SPlo, NAT_B, NAT_C,
            RPhi + SL, RPlo + SL,
            nullptr, 0, 0, nullptr, 0, 0, SPhi + 2 * SL, SPlo + 2 * SL, NAT_B, NAT_C); // S^3,4
        tgemm_kernel<<<g1, 256, TG_SMEM, s3>>>(RPhi + SL, RPlo + SL, NAT_B, NAT_C,
            SPhi + SL, SPlo + SL,
            nullptr, 0, 0, nullptr, 0, 0, RPhi + 2 * SL, RPlo + 2 * SL, NAT_B, NAT_C); // R^4
        tgemm_kernel<<<g4, 256, TG_SMEM, s3>>>(SPhi, SPlo, NAT_B, NAT_C,
            RPhi + 2 * SL, RPlo + 2 * SL,
            nullptr, 0, 0, nullptr, 0, 0, SPhi + 4 * SL, SPlo + 4 * SL, NAT_B, NAT_C); // S^5..8
        tgemm_kernel<<<g1, 256, TG_SMEM, s3>>>(RPhi + 2 * SL, RPlo + 2 * SL, NAT_B, NAT_C,
            SPhi + 3 * SL, SPlo + 3 * SL,
            nullptr, 0, 0, nullptr, 0, 0, RPhi + 3 * SL, RPlo + 3 * SL, NAT_B, NAT_C); // R^8
        tgemm_kernel<<<g8, 256, TG_SMEM, s3>>>(SPhi, SPlo, NAT_B, NAT_C,
            RPhi + 3 * SL, RPlo + 3 * SL,
            nullptr, 0, 0, nullptr, 0, 0, SPhi + 8 * SL, SPlo + 8 * SL, NAT_B, NAT_C); // S^9..16
        tgemm_kernel<<<g1, 256, TG_SMEM, s3>>>(RPhi + 3 * SL, RPlo + 3 * SL, NAT_B, NAT_C,
            SPhi + 7 * SL, SPlo + 7 * SL,
            nullptr, 0, 0, nullptr, 0, 0, RPhi + 4 * SL, RPlo + 4 * SL, NAT_B, NAT_C); // R^16
        tgemm_kernel<<<g1, 256, TG_SMEM, s3>>>(RPhi + 4 * SL, RPlo + 4 * SL, NAT_B, NAT_C,
            SPhi + 15 * SL, SPlo + 15 * SL,
            nullptr, 0, 0, nullptr, 0, 0, RPhi + 5 * SL, RPlo + 5 * SL, NAT_B, NAT_C); // R^32
        tgemm_kernel<<<g1, 256, TG_SMEM, s3>>>(SPhi + 15 * SL, SPlo + 15 * SL, NAT_B, NAT_C,
            RPhi + 4 * SL, RPlo + 4 * SL,
            nullptr, 0, 0, nullptr, 0, 0, S32hi, S32lo, NAT_B, NAT_C);               // S^32
        tgemm_kernel<<<g1, 256, TG_SMEM, s3>>>(RPhi + 5 * SL, RPlo + 5 * SL, NAT_B, NAT_C,
            S32hi, S32lo,
            nullptr, 0, 0, nullptr, 0, 0, RPhi + 6 * SL, RPlo + 6 * SL, NAT_B, NAT_C); // R^64
        tgemm_kernel<<<g1, 256, TG_SMEM, s3>>>(S32hi, S32lo, NAT_B, NAT_C,
            RPhi + 5 * SL, RPlo + 5 * SL,
            nullptr, 0, 0, nullptr, 0, 0, S64hi, S64lo, NAT_B, NAT_C);               // S^64
        tgemm_kernel<<<g1, 256, TG_SMEM, s3>>>(S64hi, S64lo, NAT_B, NAT_C,
            RPhi + 6 * SL, RPlo + 6 * SL,
            nullptr, 0, 0, W8F, NAT_B, NAT_C, nullptr, nullptr, 0, 0);               // S^128 fp32
    }
    cudaEventRecord(evPow, s3);

    // ======== main: K^T, then x split sliced by t mod 16 ========
    transpose_split_kernel<<<dim3(32, 32), 256>>>(kern, KThi, KTlo);
    cudaEventRecord(evKT, 0);
    cudaStreamWaitEvent(s2, evKT, 0);
    for (int j = 0; j < CH; j++) {
        split_gather_kernel<<<NCH * BATCH, 256>>>(x + (ll)j * 1024, TU, (ll)16 * 1024,
            Xhi + (ll)j * 1024, Xlo + (ll)j * 1024, TU, (ll)16 * 1024);
        cudaEventRecord(evXs[j], 0);
        cudaStreamWaitEvent(s2, evXs[j], 0);
        dim3 gp(8, 32);
        tgemm_kernel<<<gp, 256, TG_SMEM, s2>>>(
            Xhi + (ll)j * 1024, Xlo + (ll)j * 1024, TU, (ll)16 * 1024,
            KThi, KTlo,
            cst, 1024, 0,
            out + (ll)j * 1024, TU, CU,
            (j == 0) ? UAhi : nullptr, (j == 0) ? UAlo : nullptr, NAT_B, NAT_C);
        cudaEventRecord(evP0[j], s2);
    }

    // ======== main: phase 1 Horner chain ========
    cudaStreamWaitEvent(0, evS1, 0);
    cudaStreamWaitEvent(0, evP0[0], 0);
    {
        dim3 gp(8, 32);   // M = 4096
        for (int jj = 1; jj < CH; jj++) {
            const u16* ah = (jj & 1) ? UAhi : UBhi;
            const u16* al = (jj & 1) ? UAlo : UBlo;
            u16* oh = (jj & 1) ? UBhi : UAhi;
            u16* ol = (jj & 1) ? UBlo : UAlo;
            cudaStreamWaitEvent(0, evP0[jj], 0);
            tgemm_kernel<<<gp, 256, TG_SMEM>>>(ah, al, NAT_B, NAT_C,
                SPhi, SPlo,
                out + (ll)jj * 1024, TU, CU,
                out + (ll)jj * 1024, TU, CU,
                oh, ol, NAT_B, NAT_C);
        }
    }
    cudaEventRecord(evS, 0);   // phase 1 complete (s values final in out)

    cudaStreamWaitEvent(0, evPow, 0);

    // ---- radix-8 carry reduction: W = R^16 ----
    const float* sBase = out + (ll)(CH - 1) * 1024;

    // Snapshot even-chunk s_{2d} on s2 (off critical path). Ordered after
    // phase 1 (evS) and before the s2 residue writes by stream order.
    cudaStreamWaitEvent(s2, evS, 0);
    copy_rows_kernel<<<2048, 256, 0, s2>>>(sBase, TU, 2 * CU, sEv, NAT_B, NAT_C);
    cudaEventRecord(evSnap, s2);

    tgemm_kernel<<<dim3(8, 16), 256, TG_SMEM>>>(UBhi, UBlo, NAT_B, 2 * NAT_C,
        SPhi + 15 * SL, SPlo + 15 * SL,
        sBase + CU, TU, 2 * CU,
        sP1, NAT_B, NAT_C,
        C1hi, C1lo, NAT_B, NAT_C);                                   // combine1
    tgemm_kernel<<<dim3(8, 8), 256, TG_SMEM>>>(C1hi, C1lo, NAT_B, 2 * NAT_C,
        S32hi, S32lo,
        sP1 + NAT_C, NAT_B, 2 * NAT_C,
        sP2, NAT_B, NAT_C,
        C2hi, C2lo, NAT_B, NAT_C);                                   // combine2
    tgemm_kernel<<<dim3(8, 4), 256, TG_SMEM>>>(C2hi, C2lo, NAT_B, 2 * NAT_C,
        S64hi, S64lo,
        sP2 + NAT_C, NAT_B, 2 * NAT_C,
        sP3, NAT_B, NAT_C,
        nullptr, nullptr, 0, 0);                                     // combine3

    phase2_kernel<<<P2_CTAS, 256, P2_SMEM_FLOATS * 4>>>(
        W8F, sP3, NAT_B, NAT_C, gbuf, 8 * GB, GChi, GClo, 8 * NAT_C, 15);
    cudaEventRecord(evChain, 0);

    // s2: phase3 residue c ≡ 0 (mod 8)  (snapshot precedes by stream order)
    cudaStreamWaitEvent(s2, evChain, 0);
    tgemm_kernel<<<dim3(128, 4), 256, TG_SMEM, s2>>>(GChi, GClo, NAT_B, 8 * NAT_C,
        SPhi, SPlo,
        out, TU, 8 * CU,
        out, TU, 8 * CU,
        nullptr, nullptr, 0, 0);

    tgemm_kernel<<<dim3(8, 4), 256, TG_SMEM>>>(GChi, GClo, NAT_B, 8 * NAT_C,
        S64hi, S64lo,
        sP2, NAT_B, 2 * NAT_C,
        nullptr, 0, 0,
        GChi + 4 * NAT_C, GClo + 4 * NAT_C, NAT_B, 8 * NAT_C);       // backfill3
    cudaEventRecord(evB3, 0);

    // s2: phase3 residue c ≡ 4 (mod 8)
    cudaStreamWaitEvent(s2, evB3, 0);
    tgemm_kernel<<<dim3(128, 4), 256, TG_SMEM, s2>>>(
        GChi + 4 * NAT_C, GClo + 4 * NAT_C, NAT_B, 8 * NAT_C,
        SPhi, SPlo,
        out + 4 * CU, TU, 8 * CU,
        out + 4 * CU, TU, 8 * CU,
        nullptr, nullptr, 0, 0);

    tgemm_kernel<<<dim3(8, 8), 256, TG_SMEM>>>(GChi, GClo, NAT_B, 4 * NAT_C,
        S32hi, S32lo,
        sP1, NAT_B, 2 * NAT_C,
        nullptr, 0, 0,
        GChi + 2 * NAT_C, GClo + 2 * NAT_C, NAT_B, 4 * NAT_C);       // backfill2
    cudaEventRecord(evB2, 0);

    // s2: phase3 residue c ≡ 2 (mod 4)
    cudaStreamWaitEvent(s2, evB2, 0);
    tgemm_kernel<<<dim3(128, 8), 256, TG_SMEM, s2>>>(
        GChi + 2 * NAT_C, GClo + 2 * NAT_C, NAT_B, 4 * NAT_C,
        SPhi, SPlo,
        out + 2 * CU, TU, 4 * CU,
        out + 2 * CU, TU, 4 * CU,
        nullptr, nullptr, 0, 0);

    // backfill1 reads the SNAPSHOT of even s (race-free; gate on evSnap)
    cudaStreamWaitEvent(0, evSnap, 0);
    tgemm_kernel<<<dim3(8, 16), 256, TG_SMEM>>>(GChi, GClo, NAT_B, 2 * NAT_C,
        SPhi + 15 * SL, SPlo + 15 * SL,
        sEv, NAT_B, NAT_C,
        nullptr, 0, 0,
        GChi + NAT_C, GClo + NAT_C, NAT_B, 2 * NAT_C);               // backfill1
    cudaEventRecord(evB1, 0);

    // s2: phase3 odd residues
    cudaStreamWaitEvent(s2, evB1, 0);
    tgemm_kernel<<<dim3(128, 16), 256, TG_SMEM, s2>>>(
        GChi + NAT_C, GClo + NAT_C, NAT_B, 2 * NAT_C,
        SPhi, SPlo,
        out + CU, TU, 2 * CU,
        out + CU, TU, 2 * CU,
        nullptr, nullptr, 0, 0);

    // join s2 back into the capture stream
    cudaEventRecord(evP3, s2);
    cudaStreamWaitEvent(0, evP3, 0);
}